// round 12
// baseline (speedup 1.0000x reference)
#include <cuda_runtime.h>
#include <cuda_fp16.h>
#include <cstdint>

// Problem constants
#define BB 4
#define TT 2048
#define CC 1024
#define NH 16
#define HD 64
#define MROWS (BB * TT)   // 8192

// ---------------------------------------------------------------------------
// Scratch (device globals — no cudaMalloc allowed)
// ---------------------------------------------------------------------------
__device__ __half g_x_hi[(size_t)MROWS * CC];
__device__ __half g_wqkv_hi[(size_t)3 * CC * CC];
__device__ __half g_wqkv_lo[(size_t)3 * CC * CC];
__device__ __half g_wproj_hi[(size_t)CC * CC];
__device__ __half g_wproj_lo[(size_t)CC * CC];
__device__ __half g_qkv_hi[(size_t)MROWS * 3 * CC];
__device__ __half g_qkv_lo[(size_t)MROWS * 3 * CC];
__device__ __half g_att_hi[(size_t)MROWS * CC];

// ---------------------------------------------------------------------------
// Helpers
// ---------------------------------------------------------------------------
__device__ __forceinline__ uint32_t smem_to_u32(const void* p) {
    uint32_t a;
    asm("{ .reg .u64 t; cvta.to.shared.u64 t, %1; cvt.u32.u64 %0, t; }" : "=r"(a) : "l"(p));
    return a;
}

#define CP_ASYNC_16(dst_u32, src_ptr) \
    asm volatile("cp.async.cg.shared.global [%0], [%1], 16;" \
        :: "r"(dst_u32), "l"(src_ptr) : "memory")
#define CP_ASYNC_COMMIT() asm volatile("cp.async.commit_group;" ::: "memory")
#define CP_ASYNC_WAIT(n)  asm volatile("cp.async.wait_group %0;" :: "n"(n) : "memory")

__device__ __forceinline__ void ldsm4(uint32_t* r, uint32_t addr) {
    asm volatile("ldmatrix.sync.aligned.m8n8.x4.shared.b16 {%0,%1,%2,%3}, [%4];"
        : "=r"(r[0]), "=r"(r[1]), "=r"(r[2]), "=r"(r[3]) : "r"(addr));
}
__device__ __forceinline__ void ldsm4t(uint32_t* r, uint32_t addr) {
    asm volatile("ldmatrix.sync.aligned.m8n8.x4.trans.shared.b16 {%0,%1,%2,%3}, [%4];"
        : "=r"(r[0]), "=r"(r[1]), "=r"(r[2]), "=r"(r[3]) : "r"(addr));
}

__device__ __forceinline__ void mma_f16(float* c, const uint32_t* a, const uint32_t* b) {
    asm volatile(
        "mma.sync.aligned.m16n8k16.row.col.f32.f16.f16.f32 "
        "{%0,%1,%2,%3}, {%4,%5,%6,%7}, {%8,%9}, {%0,%1,%2,%3};"
        : "+f"(c[0]), "+f"(c[1]), "+f"(c[2]), "+f"(c[3])
        : "r"(a[0]), "r"(a[1]), "r"(a[2]), "r"(a[3]), "r"(b[0]), "r"(b[1]));
}

__device__ __forceinline__ uint32_t pack_half(float x, float y) {
    __half2 h = __floats2half2_rn(x, y);
    return *(uint32_t*)&h;
}

// ---------------------------------------------------------------------------
// fp32 -> fp16 convert (hi only)
// ---------------------------------------------------------------------------
__global__ __launch_bounds__(256) void tohalf_kernel(
    const float* __restrict__ in, __half* __restrict__ hi, int n4)
{
    int i = blockIdx.x * blockDim.x + threadIdx.x;
    if (i >= n4) return;
    float4 v = ((const float4*)in)[i];
    ((__half2*)hi)[2 * i]     = __floats2half2_rn(v.x, v.y);
    ((__half2*)hi)[2 * i + 1] = __floats2half2_rn(v.z, v.w);
}

// fp32 -> (fp16 hi, fp16 lo) split
__global__ __launch_bounds__(256) void split_half_kernel(
    const float* __restrict__ in,
    __half* __restrict__ hi, __half* __restrict__ lo, int n4)
{
    int i = blockIdx.x * blockDim.x + threadIdx.x;
    if (i >= n4) return;
    float4 v = ((const float4*)in)[i];
    __half h0 = __float2half_rn(v.x);
    __half h1 = __float2half_rn(v.y);
    __half h2 = __float2half_rn(v.z);
    __half h3 = __float2half_rn(v.w);
    __half2 hA; hA.x = h0; hA.y = h1;
    __half2 hB; hB.x = h2; hB.y = h3;
    ((__half2*)hi)[2 * i]     = hA;
    ((__half2*)hi)[2 * i + 1] = hB;
    __half2 lA = __floats2half2_rn(v.x - __half2float(h0), v.y - __half2float(h1));
    __half2 lB = __floats2half2_rn(v.z - __half2float(h2), v.w - __half2float(h3));
    ((__half2*)lo)[2 * i]     = lA;
    ((__half2*)lo)[2 * i + 1] = lB;
}

// ---------------------------------------------------------------------------
// fp16 2-term Ootomo GEMM (unchanged from round 10):
// CTA 128x128, BK=32, 8 warps, 3-stage cp.async, one sync per chunk, 2 CTAs/SM.
// ---------------------------------------------------------------------------
#define ROW_B   80
#define TILE_B  (128 * ROW_B)            // 10240
#define STAGE   (3 * TILE_B)             // 30720: Ahi, Bhi, Blo
#define NSTG    3
#define GEMM_SMEM (NSTG * STAGE)         // 92160 (x2 CTAs = 184320)

template<bool SPLIT>
__global__ __launch_bounds__(256, 2) void gemm_f16_mma(
    const __half* __restrict__ Ahi,
    const __half* __restrict__ Bhi, const __half* __restrict__ Blo,
    const float* __restrict__ bias,
    float* __restrict__ Cf, __half* __restrict__ Chi, __half* __restrict__ Clo,
    int K, int N)
{
    constexpr uint32_t AHI_O = 0;
    constexpr uint32_t BHI_O = TILE_B;
    constexpr uint32_t BLO_O = 2 * TILE_B;

    extern __shared__ __align__(16) char smem[];
    const uint32_t sbase = smem_to_u32(smem);
    const int tid = threadIdx.x;
    const int wid = tid >> 5;
    const int lid = tid & 31;
    const int wm  = wid & 1;
    const int wn  = wid >> 1;
    const int m0  = blockIdx.y * 128;
    const int n0  = blockIdx.x * 128;

    const int lr = tid >> 2;
    const int cc = tid & 3;
    const uint32_t sm_off = (uint32_t)lr * ROW_B + (uint32_t)cc * 16;
    const int gcol = cc * 8;

    const uint32_t a_off = (uint32_t)(wm * 64 + (lid & 15)) * ROW_B + (uint32_t)(lid >> 4) * 16;
    const uint32_t b_off = (uint32_t)(wn * 32 + ((lid >> 4) << 3) + (lid & 7)) * ROW_B
                         + (uint32_t)((lid >> 3) & 1) * 16;

    float acc[4][4][4];
    #pragma unroll
    for (int i = 0; i < 4; i++)
        #pragma unroll
        for (int n = 0; n < 4; n++)
            #pragma unroll
            for (int v = 0; v < 4; v++)
                acc[i][n][v] = 0.0f;

    const int NCHUNK = K >> 5;

    auto load_stage = [&](int s, int k0) {
        const uint32_t st = sbase + (uint32_t)s * STAGE;
        const size_t ga = (size_t)(m0 + lr) * K + k0 + gcol;
        const size_t gb = (size_t)(n0 + lr) * K + k0 + gcol;
        CP_ASYNC_16(st + AHI_O + sm_off,                 Ahi + ga);
        CP_ASYNC_16(st + AHI_O + sm_off + 64u * ROW_B,   Ahi + ga + (size_t)64 * K);
        CP_ASYNC_16(st + BHI_O + sm_off,                 Bhi + gb);
        CP_ASYNC_16(st + BHI_O + sm_off + 64u * ROW_B,   Bhi + gb + (size_t)64 * K);
        CP_ASYNC_16(st + BLO_O + sm_off,                 Blo + gb);
        CP_ASYNC_16(st + BLO_O + sm_off + 64u * ROW_B,   Blo + gb + (size_t)64 * K);
    };

    load_stage(0, 0);
    CP_ASYNC_COMMIT();
    load_stage(1, 32);
    CP_ASYNC_COMMIT();

    int slot = 0;
    for (int c = 0; c < NCHUNK; c++) {
        CP_ASYNC_WAIT(1);
        __syncthreads();

        int wslot = slot + 2; if (wslot >= NSTG) wslot -= NSTG;
        if (c + 2 < NCHUNK) load_stage(wslot, (c + 2) << 5);
        CP_ASYNC_COMMIT();

        const uint32_t st  = sbase + (uint32_t)slot * STAGE;
        const uint32_t aHi = st + AHI_O + a_off;
        const uint32_t bHi = st + BHI_O + b_off;
        const uint32_t bLo = st + BLO_O + b_off;

        #pragma unroll
        for (int kk = 0; kk < 2; kk++) {
            const uint32_t kb = (uint32_t)kk * 32;
            uint32_t ahi[4][4];
            #pragma unroll
            for (int i = 0; i < 4; i++)
                ldsm4(ahi[i], aHi + (uint32_t)(i * 16) * ROW_B + kb);
            uint32_t bhi[2][4], blo[2][4];
            #pragma unroll
            for (int j = 0; j < 2; j++) {
                ldsm4(bhi[j], bHi + (uint32_t)(j * 16) * ROW_B + kb);
                ldsm4(blo[j], bLo + (uint32_t)(j * 16) * ROW_B + kb);
            }
            #pragma unroll
            for (int i = 0; i < 4; i++) {
                #pragma unroll
                for (int n = 0; n < 4; n++) {
                    const uint32_t* bh = &bhi[n >> 1][(n & 1) * 2];
                    const uint32_t* bl = &blo[n >> 1][(n & 1) * 2];
                    mma_f16(acc[i][n], ahi[i], bh);
                    mma_f16(acc[i][n], ahi[i], bl);
                }
            }
        }

        if (++slot == NSTG) slot = 0;
    }

    // Epilogue
    const int trow = lid >> 2;
    const int tcol = (lid & 3) * 2;
    #pragma unroll
    for (int i = 0; i < 4; i++) {
        const int r0 = m0 + wm * 64 + i * 16 + trow;
        #pragma unroll
        for (int n = 0; n < 4; n++) {
            const int col = n0 + wn * 32 + n * 8 + tcol;
            const float b0 = bias[col], b1 = bias[col + 1];
            float v00 = acc[i][n][0] + b0, v01 = acc[i][n][1] + b1;
            float v10 = acc[i][n][2] + b0, v11 = acc[i][n][3] + b1;
            if constexpr (SPLIT) {
                __half2 h0 = __floats2half2_rn(v00, v01);
                __half2 h1 = __floats2half2_rn(v10, v11);
                __half2 l0 = __floats2half2_rn(v00 - __half2float(h0.x), v01 - __half2float(h0.y));
                __half2 l1 = __floats2half2_rn(v10 - __half2float(h1.x), v11 - __half2float(h1.y));
                *(__half2*)&Chi[(size_t)r0 * N + col]       = h0;
                *(__half2*)&Chi[(size_t)(r0 + 8) * N + col] = h1;
                *(__half2*)&Clo[(size_t)r0 * N + col]       = l0;
                *(__half2*)&Clo[(size_t)(r0 + 8) * N + col] = l1;
            } else {
                float2 f0; f0.x = v00; f0.y = v01;
                float2 f1; f1.x = v10; f1.y = v11;
                *(float2*)&Cf[(size_t)r0 * N + col]       = f0;
                *(float2*)&Cf[(size_t)(r0 + 8) * N + col] = f1;
            }
        }
    }
}

// ---------------------------------------------------------------------------
// Tensor-core flash attention (causal, fp16 2-term Ootomo).
// 3-stage cp.async KV pipeline, ONE __syncthreads per kv tile
// (same invariant as the GEMM: wait(1) -> sync -> load t+2 -> commit -> compute).
// ---------------------------------------------------------------------------
#define AROW 144
#define QT_B  (128 * AROW)
#define KVSUB (64 * AROW)
#define KVSTG (4 * KVSUB)                // 36864: khi,klo,vhi,vlo
#define ANSTG 3
#define ATT_SMEM (QT_B + ANSTG * KVSTG)  // 18432 + 110592 = 129024

__global__ __launch_bounds__(256, 1) void flash_attn_mma(
    const __half* __restrict__ Ghi, const __half* __restrict__ Glo,
    __half* __restrict__ Ohi)
{
    extern __shared__ __align__(16) char smem[];
    const uint32_t sbase = smem_to_u32(smem);
    const int tid = threadIdx.x;
    const int wid = tid >> 5;
    const int lid = tid & 31;
    const int bh  = blockIdx.y;
    const int b   = bh >> 4;
    const int h   = bh & 15;
    const int qblk = (int)gridDim.x - 1 - (int)blockIdx.x;
    const int q0   = qblk * 128;
    const int nkv  = 2 * qblk + 2;

    const uint32_t qhi_s = sbase;
    const uint32_t kv_s  = sbase + QT_B;

    // Q hi tile (grouped with kv tile 0's commit)
    {
        #pragma unroll
        for (int t = 0; t < 4; t++) {
            const int idx = tid + t * 256;
            const int row = idx >> 3;
            const int ch  = idx & 7;
            const __half* src = Ghi + (size_t)(b * TT + q0 + row) * (3 * CC) + h * HD + ch * 8;
            CP_ASYNC_16(qhi_s + (uint32_t)row * AROW + (uint32_t)ch * 16, src);
        }
    }
    auto load_kv = [&](int stage, int kv0) {
        const uint32_t st = kv_s + (uint32_t)stage * KVSTG;
        #pragma unroll
        for (int t = 0; t < 8; t++) {
            const int idx = tid + t * 256;
            const int arr = idx >> 9;            // 0:khi 1:klo 2:vhi 3:vlo
            const int rem = idx & 511;
            const int row = rem >> 3;
            const int ch  = rem & 7;
            const int colbase = ((arr >> 1) ? 2 * CC : CC) + h * HD;
            const __half* src = ((arr & 1) ? Glo : Ghi)
                + (size_t)(b * TT + kv0 + row) * (3 * CC) + colbase + ch * 8;
            CP_ASYNC_16(st + (uint32_t)arr * KVSUB + (uint32_t)row * AROW + (uint32_t)ch * 16, src);
        }
    };

    // Prime 2 stages (kv tiles 0, 1 — nkv >= 2 always)
    load_kv(0, 0);
    CP_ASYNC_COMMIT();
    load_kv(1, 64);
    CP_ASYNC_COMMIT();

    const uint32_t a_off = (uint32_t)(wid * 16 + (lid & 15)) * AROW + (uint32_t)(lid >> 4) * 16;
    const uint32_t k_off = (uint32_t)(((lid >> 4) << 3) + (lid & 7)) * AROW + (uint32_t)((lid >> 3) & 1) * 16;
    const uint32_t v_off = (uint32_t)(lid & 15) * AROW + (uint32_t)(lid >> 4) * 16;

    uint32_t qh[4][4];
    float o[8][4];
    #pragma unroll
    for (int n = 0; n < 8; n++)
        #pragma unroll
        for (int v = 0; v < 4; v++) o[n][v] = 0.0f;
    float mi0 = -__int_as_float(0x7f800000), mi1 = mi0;
    float li0 = 0.0f, li1 = 0.0f;

    const int r_lo = wid * 16 + (lid >> 2);
    const int grow0 = q0 + r_lo;
    const int grow1 = grow0 + 8;
    const float NEG_INF = -__int_as_float(0x7f800000);

    int slot = 0;
    for (int t = 0; t < nkv; t++) {
        // Invariant: 2 groups pending (tiles t, t+1 — or empties).
        CP_ASYNC_WAIT(1);
        __syncthreads();

        // Load tile t+2 into the slot tile t-1 vacated; unconditional commit.
        int wslot = slot + 2; if (wslot >= ANSTG) wslot -= ANSTG;
        if (t + 2 < nkv) load_kv(wslot, (t + 2) * 64);
        CP_ASYNC_COMMIT();

        if (t == 0) {
            #pragma unroll
            for (int kk = 0; kk < 4; kk++)
                ldsm4(qh[kk], qhi_s + a_off + (uint32_t)kk * 32);
        }

        const int kv0 = t * 64;
        const uint32_t st   = kv_s + (uint32_t)slot * KVSTG;
        const uint32_t khiB = st;
        const uint32_t kloB = st + KVSUB;
        const uint32_t vhiB = st + 2 * KVSUB;
        const uint32_t vloB = st + 3 * KVSUB;

        // ---- S = Q K^T (2-term) ----
        float s[8][4];
        #pragma unroll
        for (int n = 0; n < 8; n++)
            #pragma unroll
            for (int v = 0; v < 4; v++) s[n][v] = 0.0f;

        #pragma unroll
        for (int kk = 0; kk < 4; kk++) {
            const uint32_t kb = (uint32_t)kk * 32;
            uint32_t kh[4][4], kl[4][4];
            #pragma unroll
            for (int j = 0; j < 4; j++) {
                ldsm4(kh[j], khiB + k_off + (uint32_t)j * 16 * AROW + kb);
                ldsm4(kl[j], kloB + k_off + (uint32_t)j * 16 * AROW + kb);
            }
            #pragma unroll
            for (int n = 0; n < 8; n++) {
                const uint32_t* bh = &kh[n >> 1][(n & 1) * 2];
                const uint32_t* bl = &kl[n >> 1][(n & 1) * 2];
                mma_f16(s[n], qh[kk], bh);
                mma_f16(s[n], qh[kk], bl);
            }
        }

        // ---- scale + causal mask ----
        const bool need_mask = (kv0 + 63 > q0);
        #pragma unroll
        for (int n = 0; n < 8; n++) {
            #pragma unroll
            for (int v = 0; v < 4; v++) s[n][v] *= 0.125f;
            if (need_mask) {
                const int col = kv0 + n * 8 + (lid & 3) * 2;
                if (col > grow0)     s[n][0] = NEG_INF;
                if (col + 1 > grow0) s[n][1] = NEG_INF;
                if (col > grow1)     s[n][2] = NEG_INF;
                if (col + 1 > grow1) s[n][3] = NEG_INF;
            }
        }

        // ---- online softmax ----
        float mt0 = mi0, mt1 = mi1;
        #pragma unroll
        for (int n = 0; n < 8; n++) {
            mt0 = fmaxf(mt0, fmaxf(s[n][0], s[n][1]));
            mt1 = fmaxf(mt1, fmaxf(s[n][2], s[n][3]));
        }
        mt0 = fmaxf(mt0, __shfl_xor_sync(0xffffffffu, mt0, 1));
        mt0 = fmaxf(mt0, __shfl_xor_sync(0xffffffffu, mt0, 2));
        mt1 = fmaxf(mt1, __shfl_xor_sync(0xffffffffu, mt1, 1));
        mt1 = fmaxf(mt1, __shfl_xor_sync(0xffffffffu, mt1, 2));

        const float rs0 = __expf(mi0 - mt0);
        const float rs1 = __expf(mi1 - mt1);
        mi0 = mt0; mi1 = mt1;
        li0 *= rs0; li1 *= rs1;
        #pragma unroll
        for (int n = 0; n < 8; n++) {
            o[n][0] *= rs0; o[n][1] *= rs0;
            o[n][2] *= rs1; o[n][3] *= rs1;
        }

        uint32_t ph[4][4];
        #pragma unroll
        for (int n = 0; n < 8; n++) {
            float p0 = __expf(s[n][0] - mt0);
            float p1 = __expf(s[n][1] - mt0);
            float p2 = __expf(s[n][2] - mt1);
            float p3 = __expf(s[n][3] - mt1);
            li0 += p0 + p1;
            li1 += p2 + p3;
            const int kk = n >> 1;
            const int hi = (n & 1) * 2;
            ph[kk][hi]     = pack_half(p0, p1);
            ph[kk][hi + 1] = pack_half(p2, p3);
        }

        // ---- O += P V (2-term) ----
        #pragma unroll
        for (int kk = 0; kk < 4; kk++) {
            uint32_t vh[4][4], vl[4][4];
            #pragma unroll
            for (int jp = 0; jp < 4; jp++) {
                const uint32_t off = v_off + (uint32_t)kk * 16 * AROW + (uint32_t)jp * 32;
                ldsm4t(vh[jp], vhiB + off);
                ldsm4t(vl[jp], vloB + off);
            }
            #pragma unroll
            for (int n = 0; n < 8; n++) {
                const uint32_t* bh = &vh[n >> 1][(n & 1) * 2];
                const uint32_t* bl = &vl[n >> 1][(n & 1) * 2];
                mma_f16(o[n], ph[kk], bh);
                mma_f16(o[n], ph[kk], bl);
            }
        }

        if (++slot == ANSTG) slot = 0;
    }

    // ---- finalize ----
    li0 += __shfl_xor_sync(0xffffffffu, li0, 1);
    li0 += __shfl_xor_sync(0xffffffffu, li0, 2);
    li1 += __shfl_xor_sync(0xffffffffu, li1, 1);
    li1 += __shfl_xor_sync(0xffffffffu, li1, 2);
    const float inv0 = 1.0f / li0;
    const float inv1 = 1.0f / li1;

    #pragma unroll
    for (int n = 0; n < 8; n++) {
        const int gcol = h * HD + n * 8 + (lid & 3) * 2;
        *(__half2*)&Ohi[(size_t)(b * TT + grow0) * CC + gcol] =
            __floats2half2_rn(o[n][0] * inv0, o[n][1] * inv0);
        *(__half2*)&Ohi[(size_t)(b * TT + grow1) * CC + gcol] =
            __floats2half2_rn(o[n][2] * inv1, o[n][3] * inv1);
    }
}

// ---------------------------------------------------------------------------
extern "C" void kernel_launch(void* const* d_in, const int* in_sizes, int n_in,
                              void* d_out, int out_size)
{
    const float* x      = (const float*)d_in[0];
    const float* W_qkv  = (const float*)d_in[1];
    const float* b_qkv  = (const float*)d_in[2];
    const float* W_proj = (const float*)d_in[3];
    const float* b_proj = (const float*)d_in[4];
    float* out = (float*)d_out;

    __half *xhi, *wqh, *wql, *wph, *wpl, *qkvh, *qkvl, *atth;
    cudaGetSymbolAddress((void**)&xhi,  g_x_hi);
    cudaGetSymbolAddress((void**)&wqh,  g_wqkv_hi);
    cudaGetSymbolAddress((void**)&wql,  g_wqkv_lo);
    cudaGetSymbolAddress((void**)&wph,  g_wproj_hi);
    cudaGetSymbolAddress((void**)&wpl,  g_wproj_lo);
    cudaGetSymbolAddress((void**)&qkvh, g_qkv_hi);
    cudaGetSymbolAddress((void**)&qkvl, g_qkv_lo);
    cudaGetSymbolAddress((void**)&atth, g_att_hi);

    static bool attr_set = false;
    if (!attr_set) {
        cudaFuncSetAttribute(gemm_f16_mma<true>,
                             cudaFuncAttributeMaxDynamicSharedMemorySize, GEMM_SMEM);
        cudaFuncSetAttribute(gemm_f16_mma<false>,
                             cudaFuncAttributeMaxDynamicSharedMemorySize, GEMM_SMEM);
        cudaFuncSetAttribute(flash_attn_mma,
                             cudaFuncAttributeMaxDynamicSharedMemorySize, ATT_SMEM);
        attr_set = true;
    }

    // 0) input conversions
    {
        int n4 = (MROWS * CC) / 4;
        tohalf_kernel<<<n4 / 256, 256>>>(x, xhi, n4);
        n4 = (3 * CC * CC) / 4;
        split_half_kernel<<<n4 / 256, 256>>>(W_qkv, wqh, wql, n4);
        n4 = (CC * CC) / 4;
        split_half_kernel<<<n4 / 256, 256>>>(W_proj, wph, wpl, n4);
    }

    // 1) QKV projection (2-term), fused fp16 hi/lo output
    {
        dim3 grid((3 * CC) / 128, MROWS / 128);   // (24, 64)
        gemm_f16_mma<true><<<grid, 256, GEMM_SMEM>>>(
            xhi, wqh, wql, b_qkv, nullptr, qkvh, qkvl, CC, 3 * CC);
    }

    // 2) Causal flash attention (2-term, 3-stage pipeline), fp16 hi output
    {
        dim3 grid(TT / 128, BB * NH);             // (16, 64)
        flash_attn_mma<<<grid, 256, ATT_SMEM>>>(qkvh, qkvl, atth);
    }

    // 3) Output projection (2-term) -> fp32 d_out
    {
        dim3 grid(CC / 128, MROWS / 128);         // (8, 64)
        gemm_f16_mma<false><<<grid, 256, GEMM_SMEM>>>(
            atth, wph, wpl, b_proj, out, nullptr, nullptr, CC, CC);
    }
}

// round 14
// speedup vs baseline: 1.0799x; 1.0799x over previous
#include <cuda_runtime.h>
#include <cuda_fp16.h>
#include <cstdint>

// Problem constants
#define BB 4
#define TT 2048
#define CC 1024
#define NH 16
#define HD 64
#define MROWS (BB * TT)   // 8192

// ---------------------------------------------------------------------------
// Scratch (device globals — no cudaMalloc allowed)
// ---------------------------------------------------------------------------
__device__ __half g_x_hi[(size_t)MROWS * CC];
__device__ __half g_wqkv_hi[(size_t)3 * CC * CC];
__device__ __half g_wqkv_lo[(size_t)3 * CC * CC];
__device__ __half g_wproj_hi[(size_t)CC * CC];
__device__ __half g_wproj_lo[(size_t)CC * CC];
__device__ __half g_qkv_hi[(size_t)MROWS * 3 * CC];
__device__ __half g_qkv_lo[(size_t)MROWS * 3 * CC];
__device__ __half g_att_hi[(size_t)MROWS * CC];

// ---------------------------------------------------------------------------
// Helpers
// ---------------------------------------------------------------------------
__device__ __forceinline__ uint32_t smem_to_u32(const void* p) {
    uint32_t a;
    asm("{ .reg .u64 t; cvta.to.shared.u64 t, %1; cvt.u32.u64 %0, t; }" : "=r"(a) : "l"(p));
    return a;
}

#define CP_ASYNC_16(dst_u32, src_ptr) \
    asm volatile("cp.async.cg.shared.global [%0], [%1], 16;" \
        :: "r"(dst_u32), "l"(src_ptr) : "memory")
#define CP_ASYNC_COMMIT() asm volatile("cp.async.commit_group;" ::: "memory")
#define CP_ASYNC_WAIT(n)  asm volatile("cp.async.wait_group %0;" :: "n"(n) : "memory")

__device__ __forceinline__ void ldsm4(uint32_t* r, uint32_t addr) {
    asm volatile("ldmatrix.sync.aligned.m8n8.x4.shared.b16 {%0,%1,%2,%3}, [%4];"
        : "=r"(r[0]), "=r"(r[1]), "=r"(r[2]), "=r"(r[3]) : "r"(addr));
}
__device__ __forceinline__ void ldsm4t(uint32_t* r, uint32_t addr) {
    asm volatile("ldmatrix.sync.aligned.m8n8.x4.trans.shared.b16 {%0,%1,%2,%3}, [%4];"
        : "=r"(r[0]), "=r"(r[1]), "=r"(r[2]), "=r"(r[3]) : "r"(addr));
}

__device__ __forceinline__ void mma_f16(float* c, const uint32_t* a, const uint32_t* b) {
    asm volatile(
        "mma.sync.aligned.m16n8k16.row.col.f32.f16.f16.f32 "
        "{%0,%1,%2,%3}, {%4,%5,%6,%7}, {%8,%9}, {%0,%1,%2,%3};"
        : "+f"(c[0]), "+f"(c[1]), "+f"(c[2]), "+f"(c[3])
        : "r"(a[0]), "r"(a[1]), "r"(a[2]), "r"(a[3]), "r"(b[0]), "r"(b[1]));
}

__device__ __forceinline__ uint32_t pack_half(float x, float y) {
    __half2 h = __floats2half2_rn(x, y);
    return *(uint32_t*)&h;
}

// ---------------------------------------------------------------------------
// fp32 -> fp16 convert (hi only)
// ---------------------------------------------------------------------------
__global__ __launch_bounds__(256) void tohalf_kernel(
    const float* __restrict__ in, __half* __restrict__ hi, int n4)
{
    int i = blockIdx.x * blockDim.x + threadIdx.x;
    if (i >= n4) return;
    float4 v = ((const float4*)in)[i];
    ((__half2*)hi)[2 * i]     = __floats2half2_rn(v.x, v.y);
    ((__half2*)hi)[2 * i + 1] = __floats2half2_rn(v.z, v.w);
}

// fp32 -> (fp16 hi, fp16 lo) split
__global__ __launch_bounds__(256) void split_half_kernel(
    const float* __restrict__ in,
    __half* __restrict__ hi, __half* __restrict__ lo, int n4)
{
    int i = blockIdx.x * blockDim.x + threadIdx.x;
    if (i >= n4) return;
    float4 v = ((const float4*)in)[i];
    __half h0 = __float2half_rn(v.x);
    __half h1 = __float2half_rn(v.y);
    __half h2 = __float2half_rn(v.z);
    __half h3 = __float2half_rn(v.w);
    __half2 hA; hA.x = h0; hA.y = h1;
    __half2 hB; hB.x = h2; hB.y = h3;
    ((__half2*)hi)[2 * i]     = hA;
    ((__half2*)hi)[2 * i + 1] = hB;
    __half2 lA = __floats2half2_rn(v.x - __half2float(h0), v.y - __half2float(h1));
    __half2 lB = __floats2half2_rn(v.z - __half2float(h2), v.w - __half2float(h3));
    ((__half2*)lo)[2 * i]     = lA;
    ((__half2*)lo)[2 * i + 1] = lB;
}

// ---------------------------------------------------------------------------
// fp16 2-term Ootomo GEMM (round-10 structure):
// CTA 128x128, BK=32, 8 warps, 3-stage cp.async, one sync per chunk, 2 CTAs/SM.
// SPLIT epilogue: Clo stored only for the K third (cols [CC, 2*CC)) —
// the only region of qkv_lo the attention kernel still reads.
// ---------------------------------------------------------------------------
#define ROW_B   80
#define TILE_B  (128 * ROW_B)            // 10240
#define STAGE   (3 * TILE_B)             // 30720: Ahi, Bhi, Blo
#define NSTG    3
#define GEMM_SMEM (NSTG * STAGE)         // 92160 (x2 CTAs = 184320)

template<bool SPLIT>
__global__ __launch_bounds__(256, 2) void gemm_f16_mma(
    const __half* __restrict__ Ahi,
    const __half* __restrict__ Bhi, const __half* __restrict__ Blo,
    const float* __restrict__ bias,
    float* __restrict__ Cf, __half* __restrict__ Chi, __half* __restrict__ Clo,
    int K, int N)
{
    constexpr uint32_t AHI_O = 0;
    constexpr uint32_t BHI_O = TILE_B;
    constexpr uint32_t BLO_O = 2 * TILE_B;

    extern __shared__ __align__(16) char smem[];
    const uint32_t sbase = smem_to_u32(smem);
    const int tid = threadIdx.x;
    const int wid = tid >> 5;
    const int lid = tid & 31;
    const int wm  = wid & 1;
    const int wn  = wid >> 1;
    const int m0  = blockIdx.y * 128;
    const int n0  = blockIdx.x * 128;

    const int lr = tid >> 2;
    const int cc = tid & 3;
    const uint32_t sm_off = (uint32_t)lr * ROW_B + (uint32_t)cc * 16;
    const int gcol = cc * 8;

    const uint32_t a_off = (uint32_t)(wm * 64 + (lid & 15)) * ROW_B + (uint32_t)(lid >> 4) * 16;
    const uint32_t b_off = (uint32_t)(wn * 32 + ((lid >> 4) << 3) + (lid & 7)) * ROW_B
                         + (uint32_t)((lid >> 3) & 1) * 16;

    float acc[4][4][4];
    #pragma unroll
    for (int i = 0; i < 4; i++)
        #pragma unroll
        for (int n = 0; n < 4; n++)
            #pragma unroll
            for (int v = 0; v < 4; v++)
                acc[i][n][v] = 0.0f;

    const int NCHUNK = K >> 5;

    auto load_stage = [&](int s, int k0) {
        const uint32_t st = sbase + (uint32_t)s * STAGE;
        const size_t ga = (size_t)(m0 + lr) * K + k0 + gcol;
        const size_t gb = (size_t)(n0 + lr) * K + k0 + gcol;
        CP_ASYNC_16(st + AHI_O + sm_off,                 Ahi + ga);
        CP_ASYNC_16(st + AHI_O + sm_off + 64u * ROW_B,   Ahi + ga + (size_t)64 * K);
        CP_ASYNC_16(st + BHI_O + sm_off,                 Bhi + gb);
        CP_ASYNC_16(st + BHI_O + sm_off + 64u * ROW_B,   Bhi + gb + (size_t)64 * K);
        CP_ASYNC_16(st + BLO_O + sm_off,                 Blo + gb);
        CP_ASYNC_16(st + BLO_O + sm_off + 64u * ROW_B,   Blo + gb + (size_t)64 * K);
    };

    load_stage(0, 0);
    CP_ASYNC_COMMIT();
    load_stage(1, 32);
    CP_ASYNC_COMMIT();

    int slot = 0;
    for (int c = 0; c < NCHUNK; c++) {
        CP_ASYNC_WAIT(1);
        __syncthreads();

        int wslot = slot + 2; if (wslot >= NSTG) wslot -= NSTG;
        if (c + 2 < NCHUNK) load_stage(wslot, (c + 2) << 5);
        CP_ASYNC_COMMIT();

        const uint32_t st  = sbase + (uint32_t)slot * STAGE;
        const uint32_t aHi = st + AHI_O + a_off;
        const uint32_t bHi = st + BHI_O + b_off;
        const uint32_t bLo = st + BLO_O + b_off;

        #pragma unroll
        for (int kk = 0; kk < 2; kk++) {
            const uint32_t kb = (uint32_t)kk * 32;
            uint32_t ahi[4][4];
            #pragma unroll
            for (int i = 0; i < 4; i++)
                ldsm4(ahi[i], aHi + (uint32_t)(i * 16) * ROW_B + kb);
            uint32_t bhi[2][4], blo[2][4];
            #pragma unroll
            for (int j = 0; j < 2; j++) {
                ldsm4(bhi[j], bHi + (uint32_t)(j * 16) * ROW_B + kb);
                ldsm4(blo[j], bLo + (uint32_t)(j * 16) * ROW_B + kb);
            }
            #pragma unroll
            for (int i = 0; i < 4; i++) {
                #pragma unroll
                for (int n = 0; n < 4; n++) {
                    const uint32_t* bh = &bhi[n >> 1][(n & 1) * 2];
                    const uint32_t* bl = &blo[n >> 1][(n & 1) * 2];
                    mma_f16(acc[i][n], ahi[i], bh);
                    mma_f16(acc[i][n], ahi[i], bl);
                }
            }
        }

        if (++slot == NSTG) slot = 0;
    }

    // Epilogue
    const int trow = lid >> 2;
    const int tcol = (lid & 3) * 2;
    #pragma unroll
    for (int i = 0; i < 4; i++) {
        const int r0 = m0 + wm * 64 + i * 16 + trow;
        #pragma unroll
        for (int n = 0; n < 4; n++) {
            const int col = n0 + wn * 32 + n * 8 + tcol;
            const float b0 = bias[col], b1 = bias[col + 1];
            float v00 = acc[i][n][0] + b0, v01 = acc[i][n][1] + b1;
            float v10 = acc[i][n][2] + b0, v11 = acc[i][n][3] + b1;
            if constexpr (SPLIT) {
                __half2 h0 = __floats2half2_rn(v00, v01);
                __half2 h1 = __floats2half2_rn(v10, v11);
                *(__half2*)&Chi[(size_t)r0 * N + col]       = h0;
                *(__half2*)&Chi[(size_t)(r0 + 8) * N + col] = h1;
                // Clo only read for the K third of qkv (attention's Klo path).
                if (col >= CC && col < 2 * CC) {
                    __half2 l0 = __floats2half2_rn(v00 - __half2float(h0.x), v01 - __half2float(h0.y));
                    __half2 l1 = __floats2half2_rn(v10 - __half2float(h1.x), v11 - __half2float(h1.y));
                    *(__half2*)&Clo[(size_t)r0 * N + col]       = l0;
                    *(__half2*)&Clo[(size_t)(r0 + 8) * N + col] = l1;
                }
            } else {
                float2 f0; f0.x = v00; f0.y = v01;
                float2 f1; f1.x = v10; f1.y = v11;
                *(float2*)&Cf[(size_t)r0 * N + col]       = f0;
                *(float2*)&Cf[(size_t)(r0 + 8) * N + col] = f1;
            }
        }
    }
}

// ---------------------------------------------------------------------------
// Tensor-core flash attention (causal, fp16).
// S = Qhi*Khi + Qhi*Klo (2-term);  O += Phi*Vhi (1-term — Vlo dropped,
// error contribution <= ~1.2e-4 relative).
// 3-stage cp.async KV pipeline (khi, klo, vhi per stage), one sync per tile.
// ---------------------------------------------------------------------------
#define AROW 144
#define QT_B  (128 * AROW)
#define KVSUB (64 * AROW)
#define KVSTG (3 * KVSUB)                // 27648: khi, klo, vhi
#define ANSTG 3
#define ATT_SMEM (QT_B + ANSTG * KVSTG)  // 18432 + 82944 = 101376

__global__ __launch_bounds__(256, 1) void flash_attn_mma(
    const __half* __restrict__ Ghi, const __half* __restrict__ Glo,
    __half* __restrict__ Ohi)
{
    extern __shared__ __align__(16) char smem[];
    const uint32_t sbase = smem_to_u32(smem);
    const int tid = threadIdx.x;
    const int wid = tid >> 5;
    const int lid = tid & 31;
    const int bh  = blockIdx.y;
    const int b   = bh >> 4;
    const int h   = bh & 15;
    const int qblk = (int)gridDim.x - 1 - (int)blockIdx.x;
    const int q0   = qblk * 128;
    const int nkv  = 2 * qblk + 2;

    const uint32_t qhi_s = sbase;
    const uint32_t kv_s  = sbase + QT_B;

    // Q hi tile (grouped with kv tile 0's commit)
    {
        #pragma unroll
        for (int t = 0; t < 4; t++) {
            const int idx = tid + t * 256;
            const int row = idx >> 3;
            const int ch  = idx & 7;
            const __half* src = Ghi + (size_t)(b * TT + q0 + row) * (3 * CC) + h * HD + ch * 8;
            CP_ASYNC_16(qhi_s + (uint32_t)row * AROW + (uint32_t)ch * 16, src);
        }
    }
    // KV tile: 3 sub-tiles x 64 rows x 8 chunks = 1536 / 256 threads = 6 each
    auto load_kv = [&](int stage, int kv0) {
        const uint32_t st = kv_s + (uint32_t)stage * KVSTG;
        #pragma unroll
        for (int t = 0; t < 6; t++) {
            const int idx = tid + t * 256;
            const int arr = idx >> 9;            // 0:khi 1:klo 2:vhi
            const int rem = idx & 511;
            const int row = rem >> 3;
            const int ch  = rem & 7;
            const int colbase = ((arr == 2) ? 2 * CC : CC) + h * HD;
            const __half* src = ((arr == 1) ? Glo : Ghi)
                + (size_t)(b * TT + kv0 + row) * (3 * CC) + colbase + ch * 8;
            CP_ASYNC_16(st + (uint32_t)arr * KVSUB + (uint32_t)row * AROW + (uint32_t)ch * 16, src);
        }
    };

    // Prime 2 stages (kv tiles 0, 1 — nkv >= 2 always)
    load_kv(0, 0);
    CP_ASYNC_COMMIT();
    load_kv(1, 64);
    CP_ASYNC_COMMIT();

    const uint32_t a_off = (uint32_t)(wid * 16 + (lid & 15)) * AROW + (uint32_t)(lid >> 4) * 16;
    const uint32_t k_off = (uint32_t)(((lid >> 4) << 3) + (lid & 7)) * AROW + (uint32_t)((lid >> 3) & 1) * 16;
    const uint32_t v_off = (uint32_t)(lid & 15) * AROW + (uint32_t)(lid >> 4) * 16;

    uint32_t qh[4][4];
    float o[8][4];
    #pragma unroll
    for (int n = 0; n < 8; n++)
        #pragma unroll
        for (int v = 0; v < 4; v++) o[n][v] = 0.0f;
    float mi0 = -__int_as_float(0x7f800000), mi1 = mi0;
    float li0 = 0.0f, li1 = 0.0f;

    const int r_lo = wid * 16 + (lid >> 2);
    const int grow0 = q0 + r_lo;
    const int grow1 = grow0 + 8;
    const float NEG_INF = -__int_as_float(0x7f800000);

    int slot = 0;
    for (int t = 0; t < nkv; t++) {
        // Invariant: 2 groups pending (tiles t, t+1 — or empties).
        CP_ASYNC_WAIT(1);
        __syncthreads();

        // Load tile t+2 into the slot tile t-1 vacated; unconditional commit.
        int wslot = slot + 2; if (wslot >= ANSTG) wslot -= ANSTG;
        if (t + 2 < nkv) load_kv(wslot, (t + 2) * 64);
        CP_ASYNC_COMMIT();

        if (t == 0) {
            #pragma unroll
            for (int kk = 0; kk < 4; kk++)
                ldsm4(qh[kk], qhi_s + a_off + (uint32_t)kk * 32);
        }

        const int kv0 = t * 64;
        const uint32_t st   = kv_s + (uint32_t)slot * KVSTG;
        const uint32_t khiB = st;
        const uint32_t kloB = st + KVSUB;
        const uint32_t vhiB = st + 2 * KVSUB;

        // ---- S = Q K^T (2-term) ----
        float s[8][4];
        #pragma unroll
        for (int n = 0; n < 8; n++)
            #pragma unroll
            for (int v = 0; v < 4; v++) s[n][v] = 0.0f;

        #pragma unroll
        for (int kk = 0; kk < 4; kk++) {
            const uint32_t kb = (uint32_t)kk * 32;
            uint32_t kh[4][4], kl[4][4];
            #pragma unroll
            for (int j = 0; j < 4; j++) {
                ldsm4(kh[j], khiB + k_off + (uint32_t)j * 16 * AROW + kb);
                ldsm4(kl[j], kloB + k_off + (uint32_t)j * 16 * AROW + kb);
            }
            #pragma unroll
            for (int n = 0; n < 8; n++) {
                const uint32_t* bh = &kh[n >> 1][(n & 1) * 2];
                const uint32_t* bl = &kl[n >> 1][(n & 1) * 2];
                mma_f16(s[n], qh[kk], bh);
                mma_f16(s[n], qh[kk], bl);
            }
        }

        // ---- scale + causal mask ----
        const bool need_mask = (kv0 + 63 > q0);
        #pragma unroll
        for (int n = 0; n < 8; n++) {
            #pragma unroll
            for (int v = 0; v < 4; v++) s[n][v] *= 0.125f;
            if (need_mask) {
                const int col = kv0 + n * 8 + (lid & 3) * 2;
                if (col > grow0)     s[n][0] = NEG_INF;
                if (col + 1 > grow0) s[n][1] = NEG_INF;
                if (col > grow1)     s[n][2] = NEG_INF;
                if (col + 1 > grow1) s[n][3] = NEG_INF;
            }
        }

        // ---- online softmax ----
        float mt0 = mi0, mt1 = mi1;
        #pragma unroll
        for (int n = 0; n < 8; n++) {
            mt0 = fmaxf(mt0, fmaxf(s[n][0], s[n][1]));
            mt1 = fmaxf(mt1, fmaxf(s[n][2], s[n][3]));
        }
        mt0 = fmaxf(mt0, __shfl_xor_sync(0xffffffffu, mt0, 1));
        mt0 = fmaxf(mt0, __shfl_xor_sync(0xffffffffu, mt0, 2));
        mt1 = fmaxf(mt1, __shfl_xor_sync(0xffffffffu, mt1, 1));
        mt1 = fmaxf(mt1, __shfl_xor_sync(0xffffffffu, mt1, 2));

        const float rs0 = __expf(mi0 - mt0);
        const float rs1 = __expf(mi1 - mt1);
        mi0 = mt0; mi1 = mt1;
        li0 *= rs0; li1 *= rs1;
        #pragma unroll
        for (int n = 0; n < 8; n++) {
            o[n][0] *= rs0; o[n][1] *= rs0;
            o[n][2] *= rs1; o[n][3] *= rs1;
        }

        uint32_t ph[4][4];
        #pragma unroll
        for (int n = 0; n < 8; n++) {
            float p0 = __expf(s[n][0] - mt0);
            float p1 = __expf(s[n][1] - mt0);
            float p2 = __expf(s[n][2] - mt1);
            float p3 = __expf(s[n][3] - mt1);
            li0 += p0 + p1;
            li1 += p2 + p3;
            const int kk = n >> 1;
            const int hi = (n & 1) * 2;
            ph[kk][hi]     = pack_half(p0, p1);
            ph[kk][hi + 1] = pack_half(p2, p3);
        }

        // ---- O += P V (1-term, Vlo dropped) ----
        #pragma unroll
        for (int kk = 0; kk < 4; kk++) {
            uint32_t vh[4][4];
            #pragma unroll
            for (int jp = 0; jp < 4; jp++) {
                const uint32_t off = v_off + (uint32_t)kk * 16 * AROW + (uint32_t)jp * 32;
                ldsm4t(vh[jp], vhiB + off);
            }
            #pragma unroll
            for (int n = 0; n < 8; n++) {
                const uint32_t* bh = &vh[n >> 1][(n & 1) * 2];
                mma_f16(o[n], ph[kk], bh);
            }
        }

        if (++slot == ANSTG) slot = 0;
    }

    // ---- finalize ----
    li0 += __shfl_xor_sync(0xffffffffu, li0, 1);
    li0 += __shfl_xor_sync(0xffffffffu, li0, 2);
    li1 += __shfl_xor_sync(0xffffffffu, li1, 1);
    li1 += __shfl_xor_sync(0xffffffffu, li1, 2);
    const float inv0 = 1.0f / li0;
    const float inv1 = 1.0f / li1;

    #pragma unroll
    for (int n = 0; n < 8; n++) {
        const int gcol = h * HD + n * 8 + (lid & 3) * 2;
        *(__half2*)&Ohi[(size_t)(b * TT + grow0) * CC + gcol] =
            __floats2half2_rn(o[n][0] * inv0, o[n][1] * inv0);
        *(__half2*)&Ohi[(size_t)(b * TT + grow1) * CC + gcol] =
            __floats2half2_rn(o[n][2] * inv1, o[n][3] * inv1);
    }
}

// ---------------------------------------------------------------------------
extern "C" void kernel_launch(void* const* d_in, const int* in_sizes, int n_in,
                              void* d_out, int out_size)
{
    const float* x      = (const float*)d_in[0];
    const float* W_qkv  = (const float*)d_in[1];
    const float* b_qkv  = (const float*)d_in[2];
    const float* W_proj = (const float*)d_in[3];
    const float* b_proj = (const float*)d_in[4];
    float* out = (float*)d_out;

    __half *xhi, *wqh, *wql, *wph, *wpl, *qkvh, *qkvl, *atth;
    cudaGetSymbolAddress((void**)&xhi,  g_x_hi);
    cudaGetSymbolAddress((void**)&wqh,  g_wqkv_hi);
    cudaGetSymbolAddress((void**)&wql,  g_wqkv_lo);
    cudaGetSymbolAddress((void**)&wph,  g_wproj_hi);
    cudaGetSymbolAddress((void**)&wpl,  g_wproj_lo);
    cudaGetSymbolAddress((void**)&qkvh, g_qkv_hi);
    cudaGetSymbolAddress((void**)&qkvl, g_qkv_lo);
    cudaGetSymbolAddress((void**)&atth, g_att_hi);

    static bool attr_set = false;
    if (!attr_set) {
        cudaFuncSetAttribute(gemm_f16_mma<true>,
                             cudaFuncAttributeMaxDynamicSharedMemorySize, GEMM_SMEM);
        cudaFuncSetAttribute(gemm_f16_mma<false>,
                             cudaFuncAttributeMaxDynamicSharedMemorySize, GEMM_SMEM);
        cudaFuncSetAttribute(flash_attn_mma,
                             cudaFuncAttributeMaxDynamicSharedMemorySize, ATT_SMEM);
        attr_set = true;
    }

    // 0) input conversions
    {
        int n4 = (MROWS * CC) / 4;
        tohalf_kernel<<<n4 / 256, 256>>>(x, xhi, n4);
        n4 = (3 * CC * CC) / 4;
        split_half_kernel<<<n4 / 256, 256>>>(W_qkv, wqh, wql, n4);
        n4 = (CC * CC) / 4;
        split_half_kernel<<<n4 / 256, 256>>>(W_proj, wph, wpl, n4);
    }

    // 1) QKV projection (2-term), fused fp16 hi/lo output (lo only for K third)
    {
        dim3 grid((3 * CC) / 128, MROWS / 128);   // (24, 64)
        gemm_f16_mma<true><<<grid, 256, GEMM_SMEM>>>(
            xhi, wqh, wql, b_qkv, nullptr, qkvh, qkvl, CC, 3 * CC);
    }

    // 2) Causal flash attention (S 2-term, PV 1-term), fp16 hi output
    {
        dim3 grid(TT / 128, BB * NH);             // (16, 64)
        flash_attn_mma<<<grid, 256, ATT_SMEM>>>(qkvh, qkvl, atth);
    }

    // 3) Output projection (2-term) -> fp32 d_out
    {
        dim3 grid(CC / 128, MROWS / 128);         // (8, 64)
        gemm_f16_mma<false><<<grid, 256, GEMM_SMEM>>>(
            atth, wph, wpl, b_proj, out, nullptr, nullptr, CC, CC);
    }
}

// round 15
// speedup vs baseline: 1.5831x; 1.4660x over previous
#include <cuda_runtime.h>
#include <cuda_fp16.h>
#include <cstdint>

// Problem constants
#define BB 4
#define TT 2048
#define CC 1024
#define NH 16
#define HD 64
#define MROWS (BB * TT)   // 8192

// ---------------------------------------------------------------------------
// Scratch (device globals — no cudaMalloc allowed). Pure fp16 pipeline.
// ---------------------------------------------------------------------------
__device__ __half g_x_hi[(size_t)MROWS * CC];
__device__ __half g_wqkv_hi[(size_t)3 * CC * CC];
__device__ __half g_wproj_hi[(size_t)CC * CC];
__device__ __half g_qkv_hi[(size_t)MROWS * 3 * CC];
__device__ __half g_att_hi[(size_t)MROWS * CC];

// ---------------------------------------------------------------------------
// Helpers
// ---------------------------------------------------------------------------
__device__ __forceinline__ uint32_t smem_to_u32(const void* p) {
    uint32_t a;
    asm("{ .reg .u64 t; cvta.to.shared.u64 t, %1; cvt.u32.u64 %0, t; }" : "=r"(a) : "l"(p));
    return a;
}

#define CP_ASYNC_16(dst_u32, src_ptr) \
    asm volatile("cp.async.cg.shared.global [%0], [%1], 16;" \
        :: "r"(dst_u32), "l"(src_ptr) : "memory")
#define CP_ASYNC_COMMIT() asm volatile("cp.async.commit_group;" ::: "memory")
#define CP_ASYNC_WAIT(n)  asm volatile("cp.async.wait_group %0;" :: "n"(n) : "memory")

__device__ __forceinline__ void ldsm4(uint32_t* r, uint32_t addr) {
    asm volatile("ldmatrix.sync.aligned.m8n8.x4.shared.b16 {%0,%1,%2,%3}, [%4];"
        : "=r"(r[0]), "=r"(r[1]), "=r"(r[2]), "=r"(r[3]) : "r"(addr));
}
__device__ __forceinline__ void ldsm4t(uint32_t* r, uint32_t addr) {
    asm volatile("ldmatrix.sync.aligned.m8n8.x4.trans.shared.b16 {%0,%1,%2,%3}, [%4];"
        : "=r"(r[0]), "=r"(r[1]), "=r"(r[2]), "=r"(r[3]) : "r"(addr));
}

__device__ __forceinline__ void mma_f16(float* c, const uint32_t* a, const uint32_t* b) {
    asm volatile(
        "mma.sync.aligned.m16n8k16.row.col.f32.f16.f16.f32 "
        "{%0,%1,%2,%3}, {%4,%5,%6,%7}, {%8,%9}, {%0,%1,%2,%3};"
        : "+f"(c[0]), "+f"(c[1]), "+f"(c[2]), "+f"(c[3])
        : "r"(a[0]), "r"(a[1]), "r"(a[2]), "r"(a[3]), "r"(b[0]), "r"(b[1]));
}

__device__ __forceinline__ uint32_t pack_half(float x, float y) {
    __half2 h = __floats2half2_rn(x, y);
    return *(uint32_t*)&h;
}

// ---------------------------------------------------------------------------
// fp32 -> fp16 convert
// ---------------------------------------------------------------------------
__global__ __launch_bounds__(256) void tohalf_kernel(
    const float* __restrict__ in, __half* __restrict__ hi, int n4)
{
    int i = blockIdx.x * blockDim.x + threadIdx.x;
    if (i >= n4) return;
    float4 v = ((const float4*)in)[i];
    ((__half2*)hi)[2 * i]     = __floats2half2_rn(v.x, v.y);
    ((__half2*)hi)[2 * i + 1] = __floats2half2_rn(v.z, v.w);
}

// ---------------------------------------------------------------------------
// Plain fp16 GEMM:  C[m,n] = sum_k A[m,k]*W[n,k] + bias[n]
// CTA 128x128, BK=32, 8 warps (2m x 4n), 3-stage cp.async, one sync per chunk,
// 2 CTAs/SM.  HALF_OUT: fp16 output (for downstream fp16 consumers).
// ---------------------------------------------------------------------------
#define ROW_B   80
#define TILE_B  (128 * ROW_B)            // 10240
#define STAGE   (2 * TILE_B)             // 20480: Ahi, Bhi
#define NSTG    3
#define GEMM_SMEM (NSTG * STAGE)         // 61440 (x2 CTAs = 122880)

template<bool HALF_OUT>
__global__ __launch_bounds__(256, 2) void gemm_f16_mma(
    const __half* __restrict__ Ahi, const __half* __restrict__ Bhi,
    const float* __restrict__ bias,
    float* __restrict__ Cf, __half* __restrict__ Ch,
    int K, int N)
{
    constexpr uint32_t AHI_O = 0;
    constexpr uint32_t BHI_O = TILE_B;

    extern __shared__ __align__(16) char smem[];
    const uint32_t sbase = smem_to_u32(smem);
    const int tid = threadIdx.x;
    const int wid = tid >> 5;
    const int lid = tid & 31;
    const int wm  = wid & 1;
    const int wn  = wid >> 1;
    const int m0  = blockIdx.y * 128;
    const int n0  = blockIdx.x * 128;

    const int lr = tid >> 2;
    const int cc = tid & 3;
    const uint32_t sm_off = (uint32_t)lr * ROW_B + (uint32_t)cc * 16;
    const int gcol = cc * 8;

    const uint32_t a_off = (uint32_t)(wm * 64 + (lid & 15)) * ROW_B + (uint32_t)(lid >> 4) * 16;
    const uint32_t b_off = (uint32_t)(wn * 32 + ((lid >> 4) << 3) + (lid & 7)) * ROW_B
                         + (uint32_t)((lid >> 3) & 1) * 16;

    float acc[4][4][4];
    #pragma unroll
    for (int i = 0; i < 4; i++)
        #pragma unroll
        for (int n = 0; n < 4; n++)
            #pragma unroll
            for (int v = 0; v < 4; v++)
                acc[i][n][v] = 0.0f;

    const int NCHUNK = K >> 5;

    auto load_stage = [&](int s, int k0) {
        const uint32_t st = sbase + (uint32_t)s * STAGE;
        const size_t ga = (size_t)(m0 + lr) * K + k0 + gcol;
        const size_t gb = (size_t)(n0 + lr) * K + k0 + gcol;
        CP_ASYNC_16(st + AHI_O + sm_off,                 Ahi + ga);
        CP_ASYNC_16(st + AHI_O + sm_off + 64u * ROW_B,   Ahi + ga + (size_t)64 * K);
        CP_ASYNC_16(st + BHI_O + sm_off,                 Bhi + gb);
        CP_ASYNC_16(st + BHI_O + sm_off + 64u * ROW_B,   Bhi + gb + (size_t)64 * K);
    };

    load_stage(0, 0);
    CP_ASYNC_COMMIT();
    load_stage(1, 32);
    CP_ASYNC_COMMIT();

    int slot = 0;
    for (int c = 0; c < NCHUNK; c++) {
        CP_ASYNC_WAIT(1);
        __syncthreads();

        int wslot = slot + 2; if (wslot >= NSTG) wslot -= NSTG;
        if (c + 2 < NCHUNK) load_stage(wslot, (c + 2) << 5);
        CP_ASYNC_COMMIT();

        const uint32_t st  = sbase + (uint32_t)slot * STAGE;
        const uint32_t aHi = st + AHI_O + a_off;
        const uint32_t bHi = st + BHI_O + b_off;

        #pragma unroll
        for (int kk = 0; kk < 2; kk++) {
            const uint32_t kb = (uint32_t)kk * 32;
            uint32_t ahi[4][4];
            #pragma unroll
            for (int i = 0; i < 4; i++)
                ldsm4(ahi[i], aHi + (uint32_t)(i * 16) * ROW_B + kb);
            uint32_t bhi[2][4];
            #pragma unroll
            for (int j = 0; j < 2; j++)
                ldsm4(bhi[j], bHi + (uint32_t)(j * 16) * ROW_B + kb);
            #pragma unroll
            for (int i = 0; i < 4; i++) {
                #pragma unroll
                for (int n = 0; n < 4; n++) {
                    const uint32_t* bh = &bhi[n >> 1][(n & 1) * 2];
                    mma_f16(acc[i][n], ahi[i], bh);
                }
            }
        }

        if (++slot == NSTG) slot = 0;
    }

    // Epilogue
    const int trow = lid >> 2;
    const int tcol = (lid & 3) * 2;
    #pragma unroll
    for (int i = 0; i < 4; i++) {
        const int r0 = m0 + wm * 64 + i * 16 + trow;
        #pragma unroll
        for (int n = 0; n < 4; n++) {
            const int col = n0 + wn * 32 + n * 8 + tcol;
            const float b0 = bias[col], b1 = bias[col + 1];
            float v00 = acc[i][n][0] + b0, v01 = acc[i][n][1] + b1;
            float v10 = acc[i][n][2] + b0, v11 = acc[i][n][3] + b1;
            if constexpr (HALF_OUT) {
                *(__half2*)&Ch[(size_t)r0 * N + col]       = __floats2half2_rn(v00, v01);
                *(__half2*)&Ch[(size_t)(r0 + 8) * N + col] = __floats2half2_rn(v10, v11);
            } else {
                float2 f0; f0.x = v00; f0.y = v01;
                float2 f1; f1.x = v10; f1.y = v11;
                *(float2*)&Cf[(size_t)r0 * N + col]       = f0;
                *(float2*)&Cf[(size_t)(r0 + 8) * N + col] = f1;
            }
        }
    }
}

// ---------------------------------------------------------------------------
// Tensor-core flash attention (causal, pure fp16).
// S = Qhi*Khi (1-term);  O += Phi*Vhi (1-term).
// 3-stage cp.async KV pipeline (khi, vhi per stage), one sync per tile.
// ---------------------------------------------------------------------------
#define AROW 144
#define QT_B  (128 * AROW)
#define KVSUB (64 * AROW)
#define KVSTG (2 * KVSUB)                // 18432: khi, vhi
#define ANSTG 3
#define ATT_SMEM (QT_B + ANSTG * KVSTG)  // 18432 + 55296 = 73728

__global__ __launch_bounds__(256, 1) void flash_attn_mma(
    const __half* __restrict__ Ghi, __half* __restrict__ Ohi)
{
    extern __shared__ __align__(16) char smem[];
    const uint32_t sbase = smem_to_u32(smem);
    const int tid = threadIdx.x;
    const int wid = tid >> 5;
    const int lid = tid & 31;
    const int bh  = blockIdx.y;
    const int b   = bh >> 4;
    const int h   = bh & 15;
    const int qblk = (int)gridDim.x - 1 - (int)blockIdx.x;
    const int q0   = qblk * 128;
    const int nkv  = 2 * qblk + 2;

    const uint32_t qhi_s = sbase;
    const uint32_t kv_s  = sbase + QT_B;

    // Q hi tile (grouped with kv tile 0's commit)
    {
        #pragma unroll
        for (int t = 0; t < 4; t++) {
            const int idx = tid + t * 256;
            const int row = idx >> 3;
            const int ch  = idx & 7;
            const __half* src = Ghi + (size_t)(b * TT + q0 + row) * (3 * CC) + h * HD + ch * 8;
            CP_ASYNC_16(qhi_s + (uint32_t)row * AROW + (uint32_t)ch * 16, src);
        }
    }
    // KV tile: 2 sub-tiles x 64 rows x 8 chunks = 1024 / 256 threads = 4 each
    auto load_kv = [&](int stage, int kv0) {
        const uint32_t st = kv_s + (uint32_t)stage * KVSTG;
        #pragma unroll
        for (int t = 0; t < 4; t++) {
            const int idx = tid + t * 256;
            const int arr = idx >> 9;            // 0:khi 1:vhi
            const int rem = idx & 511;
            const int row = rem >> 3;
            const int ch  = rem & 7;
            const int colbase = (arr ? 2 * CC : CC) + h * HD;
            const __half* src = Ghi
                + (size_t)(b * TT + kv0 + row) * (3 * CC) + colbase + ch * 8;
            CP_ASYNC_16(st + (uint32_t)arr * KVSUB + (uint32_t)row * AROW + (uint32_t)ch * 16, src);
        }
    };

    // Prime 2 stages (kv tiles 0, 1 — nkv >= 2 always)
    load_kv(0, 0);
    CP_ASYNC_COMMIT();
    load_kv(1, 64);
    CP_ASYNC_COMMIT();

    const uint32_t a_off = (uint32_t)(wid * 16 + (lid & 15)) * AROW + (uint32_t)(lid >> 4) * 16;
    const uint32_t k_off = (uint32_t)(((lid >> 4) << 3) + (lid & 7)) * AROW + (uint32_t)((lid >> 3) & 1) * 16;
    const uint32_t v_off = (uint32_t)(lid & 15) * AROW + (uint32_t)(lid >> 4) * 16;

    uint32_t qh[4][4];
    float o[8][4];
    #pragma unroll
    for (int n = 0; n < 8; n++)
        #pragma unroll
        for (int v = 0; v < 4; v++) o[n][v] = 0.0f;
    float mi0 = -__int_as_float(0x7f800000), mi1 = mi0;
    float li0 = 0.0f, li1 = 0.0f;

    const int r_lo = wid * 16 + (lid >> 2);
    const int grow0 = q0 + r_lo;
    const int grow1 = grow0 + 8;
    const float NEG_INF = -__int_as_float(0x7f800000);

    int slot = 0;
    for (int t = 0; t < nkv; t++) {
        // Invariant: 2 groups pending (tiles t, t+1 — or empties).
        CP_ASYNC_WAIT(1);
        __syncthreads();

        // Load tile t+2 into the slot tile t-1 vacated; unconditional commit.
        int wslot = slot + 2; if (wslot >= ANSTG) wslot -= ANSTG;
        if (t + 2 < nkv) load_kv(wslot, (t + 2) * 64);
        CP_ASYNC_COMMIT();

        if (t == 0) {
            #pragma unroll
            for (int kk = 0; kk < 4; kk++)
                ldsm4(qh[kk], qhi_s + a_off + (uint32_t)kk * 32);
        }

        const int kv0 = t * 64;
        const uint32_t st   = kv_s + (uint32_t)slot * KVSTG;
        const uint32_t khiB = st;
        const uint32_t vhiB = st + KVSUB;

        // ---- S = Q K^T (1-term) ----
        float s[8][4];
        #pragma unroll
        for (int n = 0; n < 8; n++)
            #pragma unroll
            for (int v = 0; v < 4; v++) s[n][v] = 0.0f;

        #pragma unroll
        for (int kk = 0; kk < 4; kk++) {
            const uint32_t kb = (uint32_t)kk * 32;
            uint32_t kh[4][4];
            #pragma unroll
            for (int j = 0; j < 4; j++)
                ldsm4(kh[j], khiB + k_off + (uint32_t)j * 16 * AROW + kb);
            #pragma unroll
            for (int n = 0; n < 8; n++) {
                const uint32_t* bhp = &kh[n >> 1][(n & 1) * 2];
                mma_f16(s[n], qh[kk], bhp);
            }
        }

        // ---- scale + causal mask ----
        const bool need_mask = (kv0 + 63 > q0);
        #pragma unroll
        for (int n = 0; n < 8; n++) {
            #pragma unroll
            for (int v = 0; v < 4; v++) s[n][v] *= 0.125f;
            if (need_mask) {
                const int col = kv0 + n * 8 + (lid & 3) * 2;
                if (col > grow0)     s[n][0] = NEG_INF;
                if (col + 1 > grow0) s[n][1] = NEG_INF;
                if (col > grow1)     s[n][2] = NEG_INF;
                if (col + 1 > grow1) s[n][3] = NEG_INF;
            }
        }

        // ---- online softmax ----
        float mt0 = mi0, mt1 = mi1;
        #pragma unroll
        for (int n = 0; n < 8; n++) {
            mt0 = fmaxf(mt0, fmaxf(s[n][0], s[n][1]));
            mt1 = fmaxf(mt1, fmaxf(s[n][2], s[n][3]));
        }
        mt0 = fmaxf(mt0, __shfl_xor_sync(0xffffffffu, mt0, 1));
        mt0 = fmaxf(mt0, __shfl_xor_sync(0xffffffffu, mt0, 2));
        mt1 = fmaxf(mt1, __shfl_xor_sync(0xffffffffu, mt1, 1));
        mt1 = fmaxf(mt1, __shfl_xor_sync(0xffffffffu, mt1, 2));

        const float rs0 = __expf(mi0 - mt0);
        const float rs1 = __expf(mi1 - mt1);
        mi0 = mt0; mi1 = mt1;
        li0 *= rs0; li1 *= rs1;
        #pragma unroll
        for (int n = 0; n < 8; n++) {
            o[n][0] *= rs0; o[n][1] *= rs0;
            o[n][2] *= rs1; o[n][3] *= rs1;
        }

        uint32_t ph[4][4];
        #pragma unroll
        for (int n = 0; n < 8; n++) {
            float p0 = __expf(s[n][0] - mt0);
            float p1 = __expf(s[n][1] - mt0);
            float p2 = __expf(s[n][2] - mt1);
            float p3 = __expf(s[n][3] - mt1);
            li0 += p0 + p1;
            li1 += p2 + p3;
            const int kk = n >> 1;
            const int hi = (n & 1) * 2;
            ph[kk][hi]     = pack_half(p0, p1);
            ph[kk][hi + 1] = pack_half(p2, p3);
        }

        // ---- O += P V (1-term) ----
        #pragma unroll
        for (int kk = 0; kk < 4; kk++) {
            uint32_t vh[4][4];
            #pragma unroll
            for (int jp = 0; jp < 4; jp++) {
                const uint32_t off = v_off + (uint32_t)kk * 16 * AROW + (uint32_t)jp * 32;
                ldsm4t(vh[jp], vhiB + off);
            }
            #pragma unroll
            for (int n = 0; n < 8; n++) {
                const uint32_t* bhp = &vh[n >> 1][(n & 1) * 2];
                mma_f16(o[n], ph[kk], bhp);
            }
        }

        if (++slot == ANSTG) slot = 0;
    }

    // ---- finalize ----
    li0 += __shfl_xor_sync(0xffffffffu, li0, 1);
    li0 += __shfl_xor_sync(0xffffffffu, li0, 2);
    li1 += __shfl_xor_sync(0xffffffffu, li1, 1);
    li1 += __shfl_xor_sync(0xffffffffu, li1, 2);
    const float inv0 = 1.0f / li0;
    const float inv1 = 1.0f / li1;

    #pragma unroll
    for (int n = 0; n < 8; n++) {
        const int gcol = h * HD + n * 8 + (lid & 3) * 2;
        *(__half2*)&Ohi[(size_t)(b * TT + grow0) * CC + gcol] =
            __floats2half2_rn(o[n][0] * inv0, o[n][1] * inv0);
        *(__half2*)&Ohi[(size_t)(b * TT + grow1) * CC + gcol] =
            __floats2half2_rn(o[n][2] * inv1, o[n][3] * inv1);
    }
}

// ---------------------------------------------------------------------------
extern "C" void kernel_launch(void* const* d_in, const int* in_sizes, int n_in,
                              void* d_out, int out_size)
{
    const float* x      = (const float*)d_in[0];
    const float* W_qkv  = (const float*)d_in[1];
    const float* b_qkv  = (const float*)d_in[2];
    const float* W_proj = (const float*)d_in[3];
    const float* b_proj = (const float*)d_in[4];
    float* out = (float*)d_out;

    __half *xhi, *wqh, *wph, *qkvh, *atth;
    cudaGetSymbolAddress((void**)&xhi,  g_x_hi);
    cudaGetSymbolAddress((void**)&wqh,  g_wqkv_hi);
    cudaGetSymbolAddress((void**)&wph,  g_wproj_hi);
    cudaGetSymbolAddress((void**)&qkvh, g_qkv_hi);
    cudaGetSymbolAddress((void**)&atth, g_att_hi);

    static bool attr_set = false;
    if (!attr_set) {
        cudaFuncSetAttribute(gemm_f16_mma<true>,
                             cudaFuncAttributeMaxDynamicSharedMemorySize, GEMM_SMEM);
        cudaFuncSetAttribute(gemm_f16_mma<false>,
                             cudaFuncAttributeMaxDynamicSharedMemorySize, GEMM_SMEM);
        cudaFuncSetAttribute(flash_attn_mma,
                             cudaFuncAttributeMaxDynamicSharedMemorySize, ATT_SMEM);
        attr_set = true;
    }

    // 0) input conversions (fp32 -> fp16)
    {
        int n4 = (MROWS * CC) / 4;
        tohalf_kernel<<<n4 / 256, 256>>>(x, xhi, n4);
        n4 = (3 * CC * CC) / 4;
        tohalf_kernel<<<n4 / 256, 256>>>(W_qkv, wqh, n4);
        n4 = (CC * CC) / 4;
        tohalf_kernel<<<n4 / 256, 256>>>(W_proj, wph, n4);
    }

    // 1) QKV projection (fp16) -> fp16 qkv
    {
        dim3 grid((3 * CC) / 128, MROWS / 128);   // (24, 64)
        gemm_f16_mma<true><<<grid, 256, GEMM_SMEM>>>(
            xhi, wqh, b_qkv, nullptr, qkvh, CC, 3 * CC);
    }

    // 2) Causal flash attention (fp16) -> fp16 att
    {
        dim3 grid(TT / 128, BB * NH);             // (16, 64)
        flash_attn_mma<<<grid, 256, ATT_SMEM>>>(qkvh, atth);
    }

    // 3) Output projection (fp16) -> fp32 d_out
    {
        dim3 grid(CC / 128, MROWS / 128);         // (8, 64)
        gemm_f16_mma<false><<<grid, 256, GEMM_SMEM>>>(
            atth, wph, b_proj, out, nullptr, CC, CC);
    }
}

// round 16
// speedup vs baseline: 1.7468x; 1.1034x over previous
#include <cuda_runtime.h>
#include <cuda_fp16.h>
#include <cstdint>

// Problem constants
#define BB 4
#define TT 2048
#define CC 1024
#define NH 16
#define HD 64
#define MROWS (BB * TT)   // 8192

// ---------------------------------------------------------------------------
// Scratch (device globals — no cudaMalloc allowed). Pure fp16 pipeline.
// ---------------------------------------------------------------------------
__device__ __half g_x_hi[(size_t)MROWS * CC];
__device__ __half g_wqkv_hi[(size_t)3 * CC * CC];
__device__ __half g_wproj_hi[(size_t)CC * CC];
__device__ __half g_qkv_hi[(size_t)MROWS * 3 * CC];
__device__ __half g_att_hi[(size_t)MROWS * CC];

// ---------------------------------------------------------------------------
// Helpers
// ---------------------------------------------------------------------------
__device__ __forceinline__ uint32_t smem_to_u32(const void* p) {
    uint32_t a;
    asm("{ .reg .u64 t; cvta.to.shared.u64 t, %1; cvt.u32.u64 %0, t; }" : "=r"(a) : "l"(p));
    return a;
}

#define CP_ASYNC_16(dst_u32, src_ptr) \
    asm volatile("cp.async.cg.shared.global [%0], [%1], 16;" \
        :: "r"(dst_u32), "l"(src_ptr) : "memory")
#define CP_ASYNC_COMMIT() asm volatile("cp.async.commit_group;" ::: "memory")
#define CP_ASYNC_WAIT(n)  asm volatile("cp.async.wait_group %0;" :: "n"(n) : "memory")

__device__ __forceinline__ void ldsm4(uint32_t* r, uint32_t addr) {
    asm volatile("ldmatrix.sync.aligned.m8n8.x4.shared.b16 {%0,%1,%2,%3}, [%4];"
        : "=r"(r[0]), "=r"(r[1]), "=r"(r[2]), "=r"(r[3]) : "r"(addr));
}
__device__ __forceinline__ void ldsm4t(uint32_t* r, uint32_t addr) {
    asm volatile("ldmatrix.sync.aligned.m8n8.x4.trans.shared.b16 {%0,%1,%2,%3}, [%4];"
        : "=r"(r[0]), "=r"(r[1]), "=r"(r[2]), "=r"(r[3]) : "r"(addr));
}

__device__ __forceinline__ void mma_f16(float* c, const uint32_t* a, const uint32_t* b) {
    asm volatile(
        "mma.sync.aligned.m16n8k16.row.col.f32.f16.f16.f32 "
        "{%0,%1,%2,%3}, {%4,%5,%6,%7}, {%8,%9}, {%0,%1,%2,%3};"
        : "+f"(c[0]), "+f"(c[1]), "+f"(c[2]), "+f"(c[3])
        : "r"(a[0]), "r"(a[1]), "r"(a[2]), "r"(a[3]), "r"(b[0]), "r"(b[1]));
}

__device__ __forceinline__ uint32_t pack_half(float x, float y) {
    __half2 h = __floats2half2_rn(x, y);
    return *(uint32_t*)&h;
}

// ---------------------------------------------------------------------------
// fp32 -> fp16 convert
// ---------------------------------------------------------------------------
__global__ __launch_bounds__(256) void tohalf_kernel(
    const float* __restrict__ in, __half* __restrict__ hi, int n4)
{
    int i = blockIdx.x * blockDim.x + threadIdx.x;
    if (i >= n4) return;
    float4 v = ((const float4*)in)[i];
    ((__half2*)hi)[2 * i]     = __floats2half2_rn(v.x, v.y);
    ((__half2*)hi)[2 * i + 1] = __floats2half2_rn(v.z, v.w);
}

// ---------------------------------------------------------------------------
// Plain fp16 GEMM:  C[m,n] = sum_k A[m,k]*W[n,k] + bias[n]
// CTA 128x128, BK=64 (144B padded rows, half the syncs of BK=32),
// 8 warps (2m x 4n), 3-stage cp.async, one sync per chunk, 2 CTAs/SM.
// ---------------------------------------------------------------------------
#define ROW_B   144                      // 128B data + 16B pad
#define TILE_B  (128 * ROW_B)            // 18432
#define STAGE   (2 * TILE_B)             // 36864: Ahi, Bhi
#define NSTG    3
#define GEMM_SMEM (NSTG * STAGE)         // 110592 (x2 CTAs = 221184)

template<bool HALF_OUT>
__global__ __launch_bounds__(256, 2) void gemm_f16_mma(
    const __half* __restrict__ Ahi, const __half* __restrict__ Bhi,
    const float* __restrict__ bias,
    float* __restrict__ Cf, __half* __restrict__ Ch,
    int K, int N)
{
    extern __shared__ __align__(16) char smem[];
    const uint32_t sbase = smem_to_u32(smem);
    const int tid = threadIdx.x;
    const int wid = tid >> 5;
    const int lid = tid & 31;
    const int wm  = wid & 1;
    const int wn  = wid >> 1;
    const int m0  = blockIdx.y * 128;
    const int n0  = blockIdx.x * 128;

    const uint32_t a_off = (uint32_t)(wm * 64 + (lid & 15)) * ROW_B + (uint32_t)(lid >> 4) * 16;
    const uint32_t b_off = (uint32_t)(wn * 32 + ((lid >> 4) << 3) + (lid & 7)) * ROW_B
                         + (uint32_t)((lid >> 3) & 1) * 16;

    float acc[4][4][4];
    #pragma unroll
    for (int i = 0; i < 4; i++)
        #pragma unroll
        for (int n = 0; n < 4; n++)
            #pragma unroll
            for (int v = 0; v < 4; v++)
                acc[i][n][v] = 0.0f;

    const int NCHUNK = K >> 6;   // K/64

    // Loader: 2 tiles x 128 rows x 8 chunks(16B) = 2048 / 256 threads = 8 each
    auto load_stage = [&](int s, int k0) {
        const uint32_t st = sbase + (uint32_t)s * STAGE;
        #pragma unroll
        for (int t = 0; t < 8; t++) {
            const int idx  = tid + t * 256;
            const int tile = idx >> 10;        // 0=A, 1=B
            const int rem  = idx & 1023;
            const int row  = rem >> 3;
            const int ch   = rem & 7;
            const __half* src = (tile ? Bhi + (size_t)(n0 + row) * K
                                      : Ahi + (size_t)(m0 + row) * K) + k0 + ch * 8;
            CP_ASYNC_16(st + (uint32_t)tile * TILE_B + (uint32_t)row * ROW_B + (uint32_t)ch * 16, src);
        }
    };

    load_stage(0, 0);
    CP_ASYNC_COMMIT();
    load_stage(1, 64);
    CP_ASYNC_COMMIT();

    int slot = 0;
    for (int c = 0; c < NCHUNK; c++) {
        CP_ASYNC_WAIT(1);
        __syncthreads();

        int wslot = slot + 2; if (wslot >= NSTG) wslot -= NSTG;
        if (c + 2 < NCHUNK) load_stage(wslot, (c + 2) << 6);
        CP_ASYNC_COMMIT();

        const uint32_t st  = sbase + (uint32_t)slot * STAGE;
        const uint32_t aHi = st + a_off;
        const uint32_t bHi = st + TILE_B + b_off;

        #pragma unroll
        for (int kk = 0; kk < 4; kk++) {
            const uint32_t kb = (uint32_t)kk * 32;
            uint32_t ahi[4][4];
            #pragma unroll
            for (int i = 0; i < 4; i++)
                ldsm4(ahi[i], aHi + (uint32_t)(i * 16) * ROW_B + kb);
            uint32_t bhi[2][4];
            #pragma unroll
            for (int j = 0; j < 2; j++)
                ldsm4(bhi[j], bHi + (uint32_t)(j * 16) * ROW_B + kb);
            #pragma unroll
            for (int i = 0; i < 4; i++) {
                #pragma unroll
                for (int n = 0; n < 4; n++) {
                    const uint32_t* bh = &bhi[n >> 1][(n & 1) * 2];
                    mma_f16(acc[i][n], ahi[i], bh);
                }
            }
        }

        if (++slot == NSTG) slot = 0;
    }

    // Epilogue
    const int trow = lid >> 2;
    const int tcol = (lid & 3) * 2;
    #pragma unroll
    for (int i = 0; i < 4; i++) {
        const int r0 = m0 + wm * 64 + i * 16 + trow;
        #pragma unroll
        for (int n = 0; n < 4; n++) {
            const int col = n0 + wn * 32 + n * 8 + tcol;
            const float b0 = bias[col], b1 = bias[col + 1];
            float v00 = acc[i][n][0] + b0, v01 = acc[i][n][1] + b1;
            float v10 = acc[i][n][2] + b0, v11 = acc[i][n][3] + b1;
            if constexpr (HALF_OUT) {
                *(__half2*)&Ch[(size_t)r0 * N + col]       = __floats2half2_rn(v00, v01);
                *(__half2*)&Ch[(size_t)(r0 + 8) * N + col] = __floats2half2_rn(v10, v11);
            } else {
                float2 f0; f0.x = v00; f0.y = v01;
                float2 f1; f1.x = v10; f1.y = v11;
                *(float2*)&Cf[(size_t)r0 * N + col]       = f0;
                *(float2*)&Cf[(size_t)(r0 + 8) * N + col] = f1;
            }
        }
    }
}

// ---------------------------------------------------------------------------
// Tensor-core flash attention (causal, pure fp16).
// S = Qhi*Khi;  O += Phi*Vhi.  3-stage cp.async KV pipeline, one sync/tile.
// NOW 2 CTAs/SM (launch_bounds(256,2); smem 73728*2 = 147456 fits).
// ---------------------------------------------------------------------------
#define AROW 144
#define QT_B  (128 * AROW)
#define KVSUB (64 * AROW)
#define KVSTG (2 * KVSUB)                // 18432: khi, vhi
#define ANSTG 3
#define ATT_SMEM (QT_B + ANSTG * KVSTG)  // 18432 + 55296 = 73728

__global__ __launch_bounds__(256, 2) void flash_attn_mma(
    const __half* __restrict__ Ghi, __half* __restrict__ Ohi)
{
    extern __shared__ __align__(16) char smem[];
    const uint32_t sbase = smem_to_u32(smem);
    const int tid = threadIdx.x;
    const int wid = tid >> 5;
    const int lid = tid & 31;
    const int bh  = blockIdx.y;
    const int b   = bh >> 4;
    const int h   = bh & 15;
    const int qblk = (int)gridDim.x - 1 - (int)blockIdx.x;
    const int q0   = qblk * 128;
    const int nkv  = 2 * qblk + 2;

    const uint32_t qhi_s = sbase;
    const uint32_t kv_s  = sbase + QT_B;

    // Q hi tile (grouped with kv tile 0's commit)
    {
        #pragma unroll
        for (int t = 0; t < 4; t++) {
            const int idx = tid + t * 256;
            const int row = idx >> 3;
            const int ch  = idx & 7;
            const __half* src = Ghi + (size_t)(b * TT + q0 + row) * (3 * CC) + h * HD + ch * 8;
            CP_ASYNC_16(qhi_s + (uint32_t)row * AROW + (uint32_t)ch * 16, src);
        }
    }
    // KV tile: 2 sub-tiles x 64 rows x 8 chunks = 1024 / 256 threads = 4 each
    auto load_kv = [&](int stage, int kv0) {
        const uint32_t st = kv_s + (uint32_t)stage * KVSTG;
        #pragma unroll
        for (int t = 0; t < 4; t++) {
            const int idx = tid + t * 256;
            const int arr = idx >> 9;            // 0:khi 1:vhi
            const int rem = idx & 511;
            const int row = rem >> 3;
            const int ch  = rem & 7;
            const int colbase = (arr ? 2 * CC : CC) + h * HD;
            const __half* src = Ghi
                + (size_t)(b * TT + kv0 + row) * (3 * CC) + colbase + ch * 8;
            CP_ASYNC_16(st + (uint32_t)arr * KVSUB + (uint32_t)row * AROW + (uint32_t)ch * 16, src);
        }
    };

    load_kv(0, 0);
    CP_ASYNC_COMMIT();
    load_kv(1, 64);
    CP_ASYNC_COMMIT();

    const uint32_t a_off = (uint32_t)(wid * 16 + (lid & 15)) * AROW + (uint32_t)(lid >> 4) * 16;
    const uint32_t k_off = (uint32_t)(((lid >> 4) << 3) + (lid & 7)) * AROW + (uint32_t)((lid >> 3) & 1) * 16;
    const uint32_t v_off = (uint32_t)(lid & 15) * AROW + (uint32_t)(lid >> 4) * 16;

    uint32_t qh[4][4];
    float o[8][4];
    #pragma unroll
    for (int n = 0; n < 8; n++)
        #pragma unroll
        for (int v = 0; v < 4; v++) o[n][v] = 0.0f;
    float mi0 = -__int_as_float(0x7f800000), mi1 = mi0;
    float li0 = 0.0f, li1 = 0.0f;

    const int r_lo = wid * 16 + (lid >> 2);
    const int grow0 = q0 + r_lo;
    const int grow1 = grow0 + 8;
    const float NEG_INF = -__int_as_float(0x7f800000);

    int slot = 0;
    for (int t = 0; t < nkv; t++) {
        CP_ASYNC_WAIT(1);
        __syncthreads();

        int wslot = slot + 2; if (wslot >= ANSTG) wslot -= ANSTG;
        if (t + 2 < nkv) load_kv(wslot, (t + 2) * 64);
        CP_ASYNC_COMMIT();

        if (t == 0) {
            #pragma unroll
            for (int kk = 0; kk < 4; kk++)
                ldsm4(qh[kk], qhi_s + a_off + (uint32_t)kk * 32);
        }

        const int kv0 = t * 64;
        const uint32_t st   = kv_s + (uint32_t)slot * KVSTG;
        const uint32_t khiB = st;
        const uint32_t vhiB = st + KVSUB;

        // ---- S = Q K^T ----
        float s[8][4];
        #pragma unroll
        for (int n = 0; n < 8; n++)
            #pragma unroll
            for (int v = 0; v < 4; v++) s[n][v] = 0.0f;

        #pragma unroll
        for (int kk = 0; kk < 4; kk++) {
            const uint32_t kb = (uint32_t)kk * 32;
            uint32_t kh[4][4];
            #pragma unroll
            for (int j = 0; j < 4; j++)
                ldsm4(kh[j], khiB + k_off + (uint32_t)j * 16 * AROW + kb);
            #pragma unroll
            for (int n = 0; n < 8; n++) {
                const uint32_t* bhp = &kh[n >> 1][(n & 1) * 2];
                mma_f16(s[n], qh[kk], bhp);
            }
        }

        // ---- scale + causal mask ----
        const bool need_mask = (kv0 + 63 > q0);
        #pragma unroll
        for (int n = 0; n < 8; n++) {
            #pragma unroll
            for (int v = 0; v < 4; v++) s[n][v] *= 0.125f;
            if (need_mask) {
                const int col = kv0 + n * 8 + (lid & 3) * 2;
                if (col > grow0)     s[n][0] = NEG_INF;
                if (col + 1 > grow0) s[n][1] = NEG_INF;
                if (col > grow1)     s[n][2] = NEG_INF;
                if (col + 1 > grow1) s[n][3] = NEG_INF;
            }
        }

        // ---- online softmax ----
        float mt0 = mi0, mt1 = mi1;
        #pragma unroll
        for (int n = 0; n < 8; n++) {
            mt0 = fmaxf(mt0, fmaxf(s[n][0], s[n][1]));
            mt1 = fmaxf(mt1, fmaxf(s[n][2], s[n][3]));
        }
        mt0 = fmaxf(mt0, __shfl_xor_sync(0xffffffffu, mt0, 1));
        mt0 = fmaxf(mt0, __shfl_xor_sync(0xffffffffu, mt0, 2));
        mt1 = fmaxf(mt1, __shfl_xor_sync(0xffffffffu, mt1, 1));
        mt1 = fmaxf(mt1, __shfl_xor_sync(0xffffffffu, mt1, 2));

        const float rs0 = __expf(mi0 - mt0);
        const float rs1 = __expf(mi1 - mt1);
        mi0 = mt0; mi1 = mt1;
        li0 *= rs0; li1 *= rs1;
        #pragma unroll
        for (int n = 0; n < 8; n++) {
            o[n][0] *= rs0; o[n][1] *= rs0;
            o[n][2] *= rs1; o[n][3] *= rs1;
        }

        uint32_t ph[4][4];
        #pragma unroll
        for (int n = 0; n < 8; n++) {
            float p0 = __expf(s[n][0] - mt0);
            float p1 = __expf(s[n][1] - mt0);
            float p2 = __expf(s[n][2] - mt1);
            float p3 = __expf(s[n][3] - mt1);
            li0 += p0 + p1;
            li1 += p2 + p3;
            const int kk = n >> 1;
            const int hi = (n & 1) * 2;
            ph[kk][hi]     = pack_half(p0, p1);
            ph[kk][hi + 1] = pack_half(p2, p3);
        }

        // ---- O += P V ----
        #pragma unroll
        for (int kk = 0; kk < 4; kk++) {
            uint32_t vh[4][4];
            #pragma unroll
            for (int jp = 0; jp < 4; jp++) {
                const uint32_t off = v_off + (uint32_t)kk * 16 * AROW + (uint32_t)jp * 32;
                ldsm4t(vh[jp], vhiB + off);
            }
            #pragma unroll
            for (int n = 0; n < 8; n++) {
                const uint32_t* bhp = &vh[n >> 1][(n & 1) * 2];
                mma_f16(o[n], ph[kk], bhp);
            }
        }

        if (++slot == ANSTG) slot = 0;
    }

    // ---- finalize ----
    li0 += __shfl_xor_sync(0xffffffffu, li0, 1);
    li0 += __shfl_xor_sync(0xffffffffu, li0, 2);
    li1 += __shfl_xor_sync(0xffffffffu, li1, 1);
    li1 += __shfl_xor_sync(0xffffffffu, li1, 2);
    const float inv0 = 1.0f / li0;
    const float inv1 = 1.0f / li1;

    #pragma unroll
    for (int n = 0; n < 8; n++) {
        const int gcol = h * HD + n * 8 + (lid & 3) * 2;
        *(__half2*)&Ohi[(size_t)(b * TT + grow0) * CC + gcol] =
            __floats2half2_rn(o[n][0] * inv0, o[n][1] * inv0);
        *(__half2*)&Ohi[(size_t)(b * TT + grow1) * CC + gcol] =
            __floats2half2_rn(o[n][2] * inv1, o[n][3] * inv1);
    }
}

// ---------------------------------------------------------------------------
extern "C" void kernel_launch(void* const* d_in, const int* in_sizes, int n_in,
                              void* d_out, int out_size)
{
    const float* x      = (const float*)d_in[0];
    const float* W_qkv  = (const float*)d_in[1];
    const float* b_qkv  = (const float*)d_in[2];
    const float* W_proj = (const float*)d_in[3];
    const float* b_proj = (const float*)d_in[4];
    float* out = (float*)d_out;

    __half *xhi, *wqh, *wph, *qkvh, *atth;
    cudaGetSymbolAddress((void**)&xhi,  g_x_hi);
    cudaGetSymbolAddress((void**)&wqh,  g_wqkv_hi);
    cudaGetSymbolAddress((void**)&wph,  g_wproj_hi);
    cudaGetSymbolAddress((void**)&qkvh, g_qkv_hi);
    cudaGetSymbolAddress((void**)&atth, g_att_hi);

    static bool attr_set = false;
    if (!attr_set) {
        cudaFuncSetAttribute(gemm_f16_mma<true>,
                             cudaFuncAttributeMaxDynamicSharedMemorySize, GEMM_SMEM);
        cudaFuncSetAttribute(gemm_f16_mma<false>,
                             cudaFuncAttributeMaxDynamicSharedMemorySize, GEMM_SMEM);
        cudaFuncSetAttribute(flash_attn_mma,
                             cudaFuncAttributeMaxDynamicSharedMemorySize, ATT_SMEM);
        attr_set = true;
    }

    // 0) input conversions (fp32 -> fp16)
    {
        int n4 = (MROWS * CC) / 4;
        tohalf_kernel<<<n4 / 256, 256>>>(x, xhi, n4);
        n4 = (3 * CC * CC) / 4;
        tohalf_kernel<<<n4 / 256, 256>>>(W_qkv, wqh, n4);
        n4 = (CC * CC) / 4;
        tohalf_kernel<<<n4 / 256, 256>>>(W_proj, wph, n4);
    }

    // 1) QKV projection (fp16) -> fp16 qkv
    {
        dim3 grid((3 * CC) / 128, MROWS / 128);   // (24, 64)
        gemm_f16_mma<true><<<grid, 256, GEMM_SMEM>>>(
            xhi, wqh, b_qkv, nullptr, qkvh, CC, 3 * CC);
    }

    // 2) Causal flash attention (fp16) -> fp16 att
    {
        dim3 grid(TT / 128, BB * NH);             // (16, 64)
        flash_attn_mma<<<grid, 256, ATT_SMEM>>>(qkvh, atth);
    }

    // 3) Output projection (fp16) -> fp32 d_out
    {
        dim3 grid(CC / 128, MROWS / 128);         // (8, 64)
        gemm_f16_mma<false><<<grid, 256, GEMM_SMEM>>>(
            atth, wph, b_proj, out, nullptr, CC, CC);
    }
}

// round 17
// speedup vs baseline: 1.7720x; 1.0144x over previous
#include <cuda_runtime.h>
#include <cuda_fp16.h>
#include <cstdint>

// Problem constants
#define BB 4
#define TT 2048
#define CC 1024
#define NH 16
#define HD 64
#define MROWS (BB * TT)   // 8192

// ---------------------------------------------------------------------------
// Scratch (device globals — no cudaMalloc allowed). Pure fp16 pipeline.
// ---------------------------------------------------------------------------
__device__ __half g_x_hi[(size_t)MROWS * CC];
__device__ __half g_wqkv_hi[(size_t)3 * CC * CC];
__device__ __half g_wproj_hi[(size_t)CC * CC];
__device__ __half g_qkv_hi[(size_t)MROWS * 3 * CC];
__device__ __half g_att_hi[(size_t)MROWS * CC];

// ---------------------------------------------------------------------------
// Helpers
// ---------------------------------------------------------------------------
__device__ __forceinline__ uint32_t smem_to_u32(const void* p) {
    uint32_t a;
    asm("{ .reg .u64 t; cvta.to.shared.u64 t, %1; cvt.u32.u64 %0, t; }" : "=r"(a) : "l"(p));
    return a;
}

#define CP_ASYNC_16(dst_u32, src_ptr) \
    asm volatile("cp.async.cg.shared.global [%0], [%1], 16;" \
        :: "r"(dst_u32), "l"(src_ptr) : "memory")
#define CP_ASYNC_COMMIT() asm volatile("cp.async.commit_group;" ::: "memory")
#define CP_ASYNC_WAIT(n)  asm volatile("cp.async.wait_group %0;" :: "n"(n) : "memory")

__device__ __forceinline__ void ldsm4(uint32_t* r, uint32_t addr) {
    asm volatile("ldmatrix.sync.aligned.m8n8.x4.shared.b16 {%0,%1,%2,%3}, [%4];"
        : "=r"(r[0]), "=r"(r[1]), "=r"(r[2]), "=r"(r[3]) : "r"(addr));
}
__device__ __forceinline__ void ldsm4t(uint32_t* r, uint32_t addr) {
    asm volatile("ldmatrix.sync.aligned.m8n8.x4.trans.shared.b16 {%0,%1,%2,%3}, [%4];"
        : "=r"(r[0]), "=r"(r[1]), "=r"(r[2]), "=r"(r[3]) : "r"(addr));
}

__device__ __forceinline__ void mma_f16(float* c, const uint32_t* a, const uint32_t* b) {
    asm volatile(
        "mma.sync.aligned.m16n8k16.row.col.f32.f16.f16.f32 "
        "{%0,%1,%2,%3}, {%4,%5,%6,%7}, {%8,%9}, {%0,%1,%2,%3};"
        : "+f"(c[0]), "+f"(c[1]), "+f"(c[2]), "+f"(c[3])
        : "r"(a[0]), "r"(a[1]), "r"(a[2]), "r"(a[3]), "r"(b[0]), "r"(b[1]));
}

__device__ __forceinline__ uint32_t pack_half(float x, float y) {
    __half2 h = __floats2half2_rn(x, y);
    return *(uint32_t*)&h;
}

// ---------------------------------------------------------------------------
// Fused fp32 -> fp16 convert over three concatenated arrays.
// ---------------------------------------------------------------------------
__global__ __launch_bounds__(256) void tohalf3_kernel(
    const float* __restrict__ a, __half* __restrict__ ah, int na4,
    const float* __restrict__ b, __half* __restrict__ bh, int nb4,
    const float* __restrict__ c, __half* __restrict__ ch)
{
    int i = blockIdx.x * blockDim.x + threadIdx.x;
    const float* src;
    __half* dst;
    if (i < na4)            { src = a; dst = ah; }
    else if (i < na4 + nb4) { src = b; dst = bh; i -= na4; }
    else                    { src = c; dst = ch; i -= na4 + nb4; }
    float4 v = ((const float4*)src)[i];
    ((__half2*)dst)[2 * i]     = __floats2half2_rn(v.x, v.y);
    ((__half2*)dst)[2 * i + 1] = __floats2half2_rn(v.z, v.w);
}

// ---------------------------------------------------------------------------
// Plain fp16 GEMM:  C[m,n] = sum_k A[m,k]*W[n,k] + bias[n]
// CTA 128x128, BK=64 (144B padded rows), 8 warps (2m x 4n),
// 3-stage cp.async, one sync per chunk, 2 CTAs/SM.
// Loader addressing hoisted: one A ptr + one B ptr per thread.
// ---------------------------------------------------------------------------
#define ROW_B   144                      // 128B data + 16B pad
#define TILE_B  (128 * ROW_B)            // 18432
#define STAGE   (2 * TILE_B)             // 36864: Ahi, Bhi
#define NSTG    3
#define GEMM_SMEM (NSTG * STAGE)         // 110592 (x2 CTAs = 221184)

template<bool HALF_OUT>
__global__ __launch_bounds__(256, 2) void gemm_f16_mma(
    const __half* __restrict__ Ahi, const __half* __restrict__ Bhi,
    const float* __restrict__ bias,
    float* __restrict__ Cf, __half* __restrict__ Ch,
    int K, int N)
{
    extern __shared__ __align__(16) char smem[];
    const uint32_t sbase = smem_to_u32(smem);
    const int tid = threadIdx.x;
    const int wid = tid >> 5;
    const int lid = tid & 31;
    const int wm  = wid & 1;
    const int wn  = wid >> 1;
    const int m0  = blockIdx.y * 128;
    const int n0  = blockIdx.x * 128;

    const uint32_t a_off = (uint32_t)(wm * 64 + (lid & 15)) * ROW_B + (uint32_t)(lid >> 4) * 16;
    const uint32_t b_off = (uint32_t)(wn * 32 + ((lid >> 4) << 3) + (lid & 7)) * ROW_B
                         + (uint32_t)((lid >> 3) & 1) * 16;

    // Hoisted loader addressing: thread covers rows lrow + t*32 (t=0..3) in
    // both A and B, fixed 16B chunk lch.
    const int lrow = tid >> 3;           // 0..31
    const int lch  = tid & 7;            // 0..7
    const __half* aSrc = Ahi + (size_t)(m0 + lrow) * K + lch * 8;
    const __half* bSrc = Bhi + (size_t)(n0 + lrow) * K + lch * 8;
    const uint32_t lDst = (uint32_t)lrow * ROW_B + (uint32_t)lch * 16;

    float acc[4][4][4];
    #pragma unroll
    for (int i = 0; i < 4; i++)
        #pragma unroll
        for (int n = 0; n < 4; n++)
            #pragma unroll
            for (int v = 0; v < 4; v++)
                acc[i][n][v] = 0.0f;

    const int NCHUNK = K >> 6;   // K/64

    auto load_stage = [&](int s, int k0) {
        const uint32_t st = sbase + (uint32_t)s * STAGE + lDst;
        #pragma unroll
        for (int t = 0; t < 4; t++) {
            CP_ASYNC_16(st + (uint32_t)(t * 32) * ROW_B,
                        aSrc + (size_t)(t * 32) * K + k0);
            CP_ASYNC_16(st + TILE_B + (uint32_t)(t * 32) * ROW_B,
                        bSrc + (size_t)(t * 32) * K + k0);
        }
    };

    load_stage(0, 0);
    CP_ASYNC_COMMIT();
    load_stage(1, 64);
    CP_ASYNC_COMMIT();

    int slot = 0;
    for (int c = 0; c < NCHUNK; c++) {
        CP_ASYNC_WAIT(1);
        __syncthreads();

        int wslot = slot + 2; if (wslot >= NSTG) wslot -= NSTG;
        if (c + 2 < NCHUNK) load_stage(wslot, (c + 2) << 6);
        CP_ASYNC_COMMIT();

        const uint32_t st  = sbase + (uint32_t)slot * STAGE;
        const uint32_t aHi = st + a_off;
        const uint32_t bHi = st + TILE_B + b_off;

        #pragma unroll
        for (int kk = 0; kk < 4; kk++) {
            const uint32_t kb = (uint32_t)kk * 32;
            uint32_t ahi[4][4];
            #pragma unroll
            for (int i = 0; i < 4; i++)
                ldsm4(ahi[i], aHi + (uint32_t)(i * 16) * ROW_B + kb);
            uint32_t bhi[2][4];
            #pragma unroll
            for (int j = 0; j < 2; j++)
                ldsm4(bhi[j], bHi + (uint32_t)(j * 16) * ROW_B + kb);
            #pragma unroll
            for (int i = 0; i < 4; i++) {
                #pragma unroll
                for (int n = 0; n < 4; n++) {
                    const uint32_t* bh = &bhi[n >> 1][(n & 1) * 2];
                    mma_f16(acc[i][n], ahi[i], bh);
                }
            }
        }

        if (++slot == NSTG) slot = 0;
    }

    // Epilogue
    const int trow = lid >> 2;
    const int tcol = (lid & 3) * 2;
    #pragma unroll
    for (int i = 0; i < 4; i++) {
        const int r0 = m0 + wm * 64 + i * 16 + trow;
        #pragma unroll
        for (int n = 0; n < 4; n++) {
            const int col = n0 + wn * 32 + n * 8 + tcol;
            const float b0 = bias[col], b1 = bias[col + 1];
            float v00 = acc[i][n][0] + b0, v01 = acc[i][n][1] + b1;
            float v10 = acc[i][n][2] + b0, v11 = acc[i][n][3] + b1;
            if constexpr (HALF_OUT) {
                *(__half2*)&Ch[(size_t)r0 * N + col]       = __floats2half2_rn(v00, v01);
                *(__half2*)&Ch[(size_t)(r0 + 8) * N + col] = __floats2half2_rn(v10, v11);
            } else {
                float2 f0; f0.x = v00; f0.y = v01;
                float2 f1; f1.x = v10; f1.y = v11;
                *(float2*)&Cf[(size_t)r0 * N + col]       = f0;
                *(float2*)&Cf[(size_t)(r0 + 8) * N + col] = f1;
            }
        }
    }
}

// ---------------------------------------------------------------------------
// Tensor-core flash attention (causal, pure fp16), 2 CTAs/SM.
// S = Qhi*Khi;  O += Phi*Vhi.  3-stage cp.async KV pipeline, one sync/tile.
// KV loader addressing hoisted (one K ptr per thread; V at +CC).
// ---------------------------------------------------------------------------
#define AROW 144
#define QT_B  (128 * AROW)
#define KVSUB (64 * AROW)
#define KVSTG (2 * KVSUB)                // 18432: khi, vhi
#define ANSTG 3
#define ATT_SMEM (QT_B + ANSTG * KVSTG)  // 73728 (x2 CTAs = 147456)

__global__ __launch_bounds__(256, 2) void flash_attn_mma(
    const __half* __restrict__ Ghi, __half* __restrict__ Ohi)
{
    extern __shared__ __align__(16) char smem[];
    const uint32_t sbase = smem_to_u32(smem);
    const int tid = threadIdx.x;
    const int wid = tid >> 5;
    const int lid = tid & 31;
    const int bh  = blockIdx.y;
    const int b   = bh >> 4;
    const int h   = bh & 15;
    const int qblk = (int)gridDim.x - 1 - (int)blockIdx.x;
    const int q0   = qblk * 128;
    const int nkv  = 2 * qblk + 2;

    const uint32_t qhi_s = sbase;
    const uint32_t kv_s  = sbase + QT_B;

    // Q hi tile (grouped with kv tile 0's commit)
    {
        #pragma unroll
        for (int t = 0; t < 4; t++) {
            const int idx = tid + t * 256;
            const int row = idx >> 3;
            const int ch  = idx & 7;
            const __half* src = Ghi + (size_t)(b * TT + q0 + row) * (3 * CC) + h * HD + ch * 8;
            CP_ASYNC_16(qhi_s + (uint32_t)row * AROW + (uint32_t)ch * 16, src);
        }
    }

    // Hoisted KV loader: thread covers rows lrow + t*32 (t=0..1) in K and V.
    const int lrow = tid >> 3;           // 0..31
    const int lch  = tid & 7;            // 0..7
    const __half* kSrc = Ghi + (size_t)(b * TT + lrow) * (3 * CC) + CC + h * HD + lch * 8;
    const uint32_t kDst = (uint32_t)lrow * AROW + (uint32_t)lch * 16;

    auto load_kv = [&](int stage, int kv0) {
        const uint32_t st = kv_s + (uint32_t)stage * KVSTG + kDst;
        const __half* src = kSrc + (size_t)kv0 * (3 * CC);
        #pragma unroll
        for (int t = 0; t < 2; t++) {
            CP_ASYNC_16(st + (uint32_t)(t * 32) * AROW,
                        src + (size_t)(t * 32) * (3 * CC));
            CP_ASYNC_16(st + KVSUB + (uint32_t)(t * 32) * AROW,
                        src + CC + (size_t)(t * 32) * (3 * CC));
        }
    };

    load_kv(0, 0);
    CP_ASYNC_COMMIT();
    load_kv(1, 64);
    CP_ASYNC_COMMIT();

    const uint32_t a_off = (uint32_t)(wid * 16 + (lid & 15)) * AROW + (uint32_t)(lid >> 4) * 16;
    const uint32_t k_off = (uint32_t)(((lid >> 4) << 3) + (lid & 7)) * AROW + (uint32_t)((lid >> 3) & 1) * 16;
    const uint32_t v_off = (uint32_t)(lid & 15) * AROW + (uint32_t)(lid >> 4) * 16;

    uint32_t qh[4][4];
    float o[8][4];
    #pragma unroll
    for (int n = 0; n < 8; n++)
        #pragma unroll
        for (int v = 0; v < 4; v++) o[n][v] = 0.0f;
    float mi0 = -__int_as_float(0x7f800000), mi1 = mi0;
    float li0 = 0.0f, li1 = 0.0f;

    const int r_lo = wid * 16 + (lid >> 2);
    const int grow0 = q0 + r_lo;
    const int grow1 = grow0 + 8;
    const float NEG_INF = -__int_as_float(0x7f800000);

    int slot = 0;
    for (int t = 0; t < nkv; t++) {
        CP_ASYNC_WAIT(1);
        __syncthreads();

        int wslot = slot + 2; if (wslot >= ANSTG) wslot -= ANSTG;
        if (t + 2 < nkv) load_kv(wslot, (t + 2) * 64);
        CP_ASYNC_COMMIT();

        if (t == 0) {
            #pragma unroll
            for (int kk = 0; kk < 4; kk++)
                ldsm4(qh[kk], qhi_s + a_off + (uint32_t)kk * 32);
        }

        const int kv0 = t * 64;
        const uint32_t st   = kv_s + (uint32_t)slot * KVSTG;
        const uint32_t khiB = st;
        const uint32_t vhiB = st + KVSUB;

        // ---- S = Q K^T ----
        float s[8][4];
        #pragma unroll
        for (int n = 0; n < 8; n++)
            #pragma unroll
            for (int v = 0; v < 4; v++) s[n][v] = 0.0f;

        #pragma unroll
        for (int kk = 0; kk < 4; kk++) {
            const uint32_t kb = (uint32_t)kk * 32;
            uint32_t kh[4][4];
            #pragma unroll
            for (int j = 0; j < 4; j++)
                ldsm4(kh[j], khiB + k_off + (uint32_t)j * 16 * AROW + kb);
            #pragma unroll
            for (int n = 0; n < 8; n++) {
                const uint32_t* bhp = &kh[n >> 1][(n & 1) * 2];
                mma_f16(s[n], qh[kk], bhp);
            }
        }

        // ---- scale + causal mask ----
        const bool need_mask = (kv0 + 63 > q0);
        #pragma unroll
        for (int n = 0; n < 8; n++) {
            #pragma unroll
            for (int v = 0; v < 4; v++) s[n][v] *= 0.125f;
            if (need_mask) {
                const int col = kv0 + n * 8 + (lid & 3) * 2;
                if (col > grow0)     s[n][0] = NEG_INF;
                if (col + 1 > grow0) s[n][1] = NEG_INF;
                if (col > grow1)     s[n][2] = NEG_INF;
                if (col + 1 > grow1) s[n][3] = NEG_INF;
            }
        }

        // ---- online softmax ----
        float mt0 = mi0, mt1 = mi1;
        #pragma unroll
        for (int n = 0; n < 8; n++) {
            mt0 = fmaxf(mt0, fmaxf(s[n][0], s[n][1]));
            mt1 = fmaxf(mt1, fmaxf(s[n][2], s[n][3]));
        }
        mt0 = fmaxf(mt0, __shfl_xor_sync(0xffffffffu, mt0, 1));
        mt0 = fmaxf(mt0, __shfl_xor_sync(0xffffffffu, mt0, 2));
        mt1 = fmaxf(mt1, __shfl_xor_sync(0xffffffffu, mt1, 1));
        mt1 = fmaxf(mt1, __shfl_xor_sync(0xffffffffu, mt1, 2));

        const float rs0 = __expf(mi0 - mt0);
        const float rs1 = __expf(mi1 - mt1);
        mi0 = mt0; mi1 = mt1;
        li0 *= rs0; li1 *= rs1;
        #pragma unroll
        for (int n = 0; n < 8; n++) {
            o[n][0] *= rs0; o[n][1] *= rs0;
            o[n][2] *= rs1; o[n][3] *= rs1;
        }

        uint32_t ph[4][4];
        #pragma unroll
        for (int n = 0; n < 8; n++) {
            float p0 = __expf(s[n][0] - mt0);
            float p1 = __expf(s[n][1] - mt0);
            float p2 = __expf(s[n][2] - mt1);
            float p3 = __expf(s[n][3] - mt1);
            li0 += p0 + p1;
            li1 += p2 + p3;
            const int kk = n >> 1;
            const int hi = (n & 1) * 2;
            ph[kk][hi]     = pack_half(p0, p1);
            ph[kk][hi + 1] = pack_half(p2, p3);
        }

        // ---- O += P V ----
        #pragma unroll
        for (int kk = 0; kk < 4; kk++) {
            uint32_t vh[4][4];
            #pragma unroll
            for (int jp = 0; jp < 4; jp++) {
                const uint32_t off = v_off + (uint32_t)kk * 16 * AROW + (uint32_t)jp * 32;
                ldsm4t(vh[jp], vhiB + off);
            }
            #pragma unroll
            for (int n = 0; n < 8; n++) {
                const uint32_t* bhp = &vh[n >> 1][(n & 1) * 2];
                mma_f16(o[n], ph[kk], bhp);
            }
        }

        if (++slot == ANSTG) slot = 0;
    }

    // ---- finalize ----
    li0 += __shfl_xor_sync(0xffffffffu, li0, 1);
    li0 += __shfl_xor_sync(0xffffffffu, li0, 2);
    li1 += __shfl_xor_sync(0xffffffffu, li1, 1);
    li1 += __shfl_xor_sync(0xffffffffu, li1, 2);
    const float inv0 = 1.0f / li0;
    const float inv1 = 1.0f / li1;

    #pragma unroll
    for (int n = 0; n < 8; n++) {
        const int gcol = h * HD + n * 8 + (lid & 3) * 2;
        *(__half2*)&Ohi[(size_t)(b * TT + grow0) * CC + gcol] =
            __floats2half2_rn(o[n][0] * inv0, o[n][1] * inv0);
        *(__half2*)&Ohi[(size_t)(b * TT + grow1) * CC + gcol] =
            __floats2half2_rn(o[n][2] * inv1, o[n][3] * inv1);
    }
}

// ---------------------------------------------------------------------------
extern "C" void kernel_launch(void* const* d_in, const int* in_sizes, int n_in,
                              void* d_out, int out_size)
{
    const float* x      = (const float*)d_in[0];
    const float* W_qkv  = (const float*)d_in[1];
    const float* b_qkv  = (const float*)d_in[2];
    const float* W_proj = (const float*)d_in[3];
    const float* b_proj = (const float*)d_in[4];
    float* out = (float*)d_out;

    __half *xhi, *wqh, *wph, *qkvh, *atth;
    cudaGetSymbolAddress((void**)&xhi,  g_x_hi);
    cudaGetSymbolAddress((void**)&wqh,  g_wqkv_hi);
    cudaGetSymbolAddress((void**)&wph,  g_wproj_hi);
    cudaGetSymbolAddress((void**)&qkvh, g_qkv_hi);
    cudaGetSymbolAddress((void**)&atth, g_att_hi);

    static bool attr_set = false;
    if (!attr_set) {
        cudaFuncSetAttribute(gemm_f16_mma<true>,
                             cudaFuncAttributeMaxDynamicSharedMemorySize, GEMM_SMEM);
        cudaFuncSetAttribute(gemm_f16_mma<false>,
                             cudaFuncAttributeMaxDynamicSharedMemorySize, GEMM_SMEM);
        cudaFuncSetAttribute(flash_attn_mma,
                             cudaFuncAttributeMaxDynamicSharedMemorySize, ATT_SMEM);
        attr_set = true;
    }

    // 0) fused input conversions (x, W_qkv, W_proj -> fp16)
    {
        const int na4 = (MROWS * CC) / 4;        // 2,097,152
        const int nb4 = (3 * CC * CC) / 4;       //   786,432
        const int nc4 = (CC * CC) / 4;           //   262,144
        const int total = na4 + nb4 + nc4;       // 3,145,728
        tohalf3_kernel<<<total / 256, 256>>>(x, xhi, na4, W_qkv, wqh, nb4, W_proj, wph);
    }

    // 1) QKV projection (fp16) -> fp16 qkv
    {
        dim3 grid((3 * CC) / 128, MROWS / 128);   // (24, 64)
        gemm_f16_mma<true><<<grid, 256, GEMM_SMEM>>>(
            xhi, wqh, b_qkv, nullptr, qkvh, CC, 3 * CC);
    }

    // 2) Causal flash attention (fp16) -> fp16 att
    {
        dim3 grid(TT / 128, BB * NH);             // (16, 64)
        flash_attn_mma<<<grid, 256, ATT_SMEM>>>(qkvh, atth);
    }

    // 3) Output projection (fp16) -> fp32 d_out
    {
        dim3 grid(CC / 128, MROWS / 128);         // (8, 64)
        gemm_f16_mma<false><<<grid, 256, GEMM_SMEM>>>(
            atth, wph, b_proj, out, nullptr, CC, CC);
    }
}